// round 11
// baseline (speedup 1.0000x reference)
#include <cuda_runtime.h>
#include <cuda_fp16.h>
#include <cstdint>

// Problem constants
#define BATCH 4
#define SEQ   4096
#define DIM   1024
#define NH    16
#define HD    64
#define KVC   8               // split-S chunks for kv accumulation
#define SCH   (SEQ / KVC)     // 512

// GEMM tile config
#define GK      1024
#define TM      128
#define TN      128
#define BK      32                   // K elements per chunk
#define NCHUNK  (GK / BK)            // 32
#define RS      40                   // smem row stride in fp16 (32 data + 8 pad) = 80B
#define TILE_B  (128 * RS * 2)       // 10240 bytes per tile
#define STAGE_B (2 * TILE_B)         // A, B = 20480 bytes
#define NSTAGE  3
#define GSMEM   (NSTAGE * STAGE_B)   // 61440 bytes -> 3 CTAs/SM

// kv tile config
#define RSK     72                   // kv smem row stride halves (64 + 8 pad) = 144B
#define KVTILE  (64 * RSK * 2)       // 9216 bytes

// ---------------------------------------------------------------------------
// Scratch
// ---------------------------------------------------------------------------
__device__ __half g_x16[BATCH * SEQ * DIM];
__device__ __half g_qw16[DIM * DIM], g_kw16[DIM * DIM], g_vw16[DIM * DIM];
__device__ __half g_q16[BATCH * SEQ * DIM];
__device__ __half g_k16[BATCH * SEQ * DIM];
__device__ __half g_v16[BATCH * SEQ * DIM];
__device__ float g_kvp[BATCH * NH * KVC * HD * HD];
__device__ __half g_mtf[BATCH * DIM * DIM];

// ---------------------------------------------------------------------------
// PTX helpers
// ---------------------------------------------------------------------------
__device__ __forceinline__ uint32_t smem_u32(const void* p) {
    uint32_t a;
    asm("{ .reg .u64 t; cvta.to.shared.u64 t, %1; cvt.u32.u64 %0, t; }" : "=r"(a) : "l"(p));
    return a;
}

#define CP_ASYNC16(s, g) asm volatile("cp.async.cg.shared.global [%0], [%1], 16;" :: "r"(s), "l"(g))
#define CP_COMMIT()      asm volatile("cp.async.commit_group;" ::: "memory")
#define CP_WAIT1()       asm volatile("cp.async.wait_group 1;" ::: "memory")
#define CP_WAIT0()       asm volatile("cp.async.wait_group 0;" ::: "memory")

#define LDSM_X4(r0, r1, r2, r3, a) \
    asm volatile("ldmatrix.sync.aligned.m8n8.x4.shared.b16 {%0,%1,%2,%3}, [%4];" \
                 : "=r"(r0), "=r"(r1), "=r"(r2), "=r"(r3) : "r"(a))
#define LDSM_X4_T(r0, r1, r2, r3, a) \
    asm volatile("ldmatrix.sync.aligned.m8n8.x4.trans.shared.b16 {%0,%1,%2,%3}, [%4];" \
                 : "=r"(r0), "=r"(r1), "=r"(r2), "=r"(r3) : "r"(a))

// D += A * B  (m16n8k16, fp16 in, f32 accum)
__device__ __forceinline__ void mma16816(float* c, const uint32_t* a, const uint32_t* b) {
    asm volatile(
        "mma.sync.aligned.m16n8k16.row.col.f32.f16.f16.f32 "
        "{%0,%1,%2,%3}, {%4,%5,%6,%7}, {%8,%9}, {%0,%1,%2,%3};"
        : "+f"(c[0]), "+f"(c[1]), "+f"(c[2]), "+f"(c[3])
        : "r"(a[0]), "r"(a[1]), "r"(a[2]), "r"(a[3]), "r"(b[0]), "r"(b[1]));
}

__device__ __forceinline__ uint32_t pack2h(float lo_v, float hi_v) {
    uint32_t r;
    asm("cvt.rn.f16x2.f32 %0, %1, %2;" : "=r"(r) : "f"(hi_v), "f"(lo_v));
    return r;
}

// ---------------------------------------------------------------------------
// Round kernels: fp32 -> fp16
// ---------------------------------------------------------------------------
__global__ void round_f32h(const float* __restrict__ s, __half* __restrict__ o, long n)
{
    long i = ((long)blockIdx.x * blockDim.x + threadIdx.x) * 4;
    if (i >= n) return;
    float4 v = *(const float4*)(s + i);
    *(uint2*)(o + i) = make_uint2(pack2h(v.x, v.y), pack2h(v.z, v.w));
}

__global__ void round_w3(const float* __restrict__ s0, const float* __restrict__ s1,
                         const float* __restrict__ s2,
                         __half* __restrict__ o0, __half* __restrict__ o1,
                         __half* __restrict__ o2, long n)
{
    const float* s = (blockIdx.y == 0) ? s0 : (blockIdx.y == 1) ? s1 : s2;
    __half*      o = (blockIdx.y == 0) ? o0 : (blockIdx.y == 1) ? o1 : o2;
    long i = ((long)blockIdx.x * blockDim.x + threadIdx.x) * 4;
    if (i >= n) return;
    float4 v = *(const float4*)(s + i);
    *(uint2*)(o + i) = make_uint2(pack2h(v.x, v.y), pack2h(v.z, v.w));
}

// ---------------------------------------------------------------------------
// Shared GEMM mainloop: 128 threads, 4 warps (2x2), warp tile 64x64.
// acc[4][8][4] += A_tile[m0:128,:] * B_tile[n0:128,:]^T. BK=32, 3-stage ring.
// Register-lean addressing: A pointers + constant A->B delta.
// ---------------------------------------------------------------------------
__device__ __forceinline__ void gemm_mainloop(
    const __half* __restrict__ A, const __half* __restrict__ B,
    uint32_t smem_addr, int m0, int n0, int tid, float acc[4][8][4])
{
    const int wid  = tid >> 5;
    const int lane = tid & 31;

    // cp.async geometry: tile = 128 rows x 4 (16B chunks); 4 slots/thread/tile.
    // B source = A source + delta (same row/ck layout, different base & tile row).
    const long delta = (B - A) + (long)(n0 - m0) * GK;
    uint32_t so[4];
    const __half* pa[4];
    #pragma unroll
    for (int i = 0; i < 4; ++i) {
        int idx = i * 128 + tid;
        int row = idx >> 2, ck = idx & 3;
        so[i] = (uint32_t)(row * RS + ck * 8) * 2;
        pa[i] = A + (long)(m0 + row) * GK + ck * 8;
    }

    auto load_stage = [&](int kt, int buf) {
        const uint32_t sb = smem_addr + buf * STAGE_B;
        const long ko = (long)kt * BK;
        #pragma unroll
        for (int i = 0; i < 4; ++i) CP_ASYNC16(sb + so[i],          pa[i] + ko);
        #pragma unroll
        for (int i = 0; i < 4; ++i) CP_ASYNC16(sb + TILE_B + so[i], pa[i] + delta + ko);
    };

    load_stage(0, 0); CP_COMMIT();
    load_stage(1, 1); CP_COMMIT();

    // Warp tiling: 2x2 warp grid, each warp 64x64
    const int wm = (wid >> 1) * 64;
    const int wn = (wid & 1) * 64;

    // ldmatrix per-lane address parts
    const uint32_t rA  = lane & 15;
    const uint32_t kAp = (uint32_t)(lane >> 4) << 4;
    const uint32_t rB  = (lane & 7) + ((lane & 16) >> 1);
    const uint32_t kBp = (lane & 8) << 1;

    const uint32_t offA0 = (uint32_t)(wm + rA) * (RS * 2) + kAp;
    const uint32_t offB0 = (uint32_t)(wn + rB) * (RS * 2) + kBp + TILE_B;

    for (int kt = 0; kt < NCHUNK; ++kt) {
        CP_WAIT1();
        __syncthreads();

        if (kt + 2 < NCHUNK) load_stage(kt + 2, (kt + 2) % 3);
        CP_COMMIT();

        const uint32_t Sb = smem_addr + (kt % 3) * STAGE_B;

        #pragma unroll
        for (int ks2 = 0; ks2 < 2; ++ks2) {
            const uint32_t kb = ks2 * 32;   // 16 k-elements = 32 bytes
            uint32_t af[4][4], bf[8][2];

            #pragma unroll
            for (int mt = 0; mt < 4; ++mt)
                LDSM_X4(af[mt][0], af[mt][1], af[mt][2], af[mt][3],
                        Sb + kb + offA0 + mt * (16 * RS * 2));
            #pragma unroll
            for (int ntp = 0; ntp < 4; ++ntp) {
                const uint32_t ba = Sb + kb + offB0 + ntp * (16 * RS * 2);
                LDSM_X4(bf[2*ntp][0], bf[2*ntp][1], bf[2*ntp+1][0], bf[2*ntp+1][1], ba);
            }

            #pragma unroll
            for (int mt = 0; mt < 4; ++mt)
                #pragma unroll
                for (int nt = 0; nt < 8; ++nt)
                    mma16816(acc[mt][nt], af[mt], bf[nt]);
        }
    }
}

// ---------------------------------------------------------------------------
// Fused QKV GEMM: blockIdx.z selects (W, bias, out, relu). fp16 out.
// ---------------------------------------------------------------------------
__global__ __launch_bounds__(128, 3)
void gemm_qkv(const float* __restrict__ qb, const float* __restrict__ kb,
              const float* __restrict__ vb)
{
    extern __shared__ char smem[];
    const uint32_t smem_addr = smem_u32(smem);

    const int tid = threadIdx.x;
    const int z   = blockIdx.z;
    const int m0  = blockIdx.y * TM;
    const int n0  = blockIdx.x * TN;

    const __half* B    = (z == 0) ? g_qw16 : (z == 1) ? g_kw16 : g_vw16;
    const float*  bias = (z == 0) ? qb     : (z == 1) ? kb     : vb;
    __half*       outH = (z == 0) ? g_q16  : (z == 1) ? g_k16  : g_v16;
    const bool    relu = (z != 2);

    float acc[4][8][4] = {};
    gemm_mainloop(g_x16, B, smem_addr, m0, n0, tid, acc);

    const int wid  = tid >> 5;
    const int lane = tid & 31;
    const int wm = (wid >> 1) * 64, wn = (wid & 1) * 64;
    const int lr = lane >> 2, lc2 = (lane & 3) * 2;

    #pragma unroll
    for (int mt = 0; mt < 4; ++mt) {
        #pragma unroll
        for (int nt = 0; nt < 8; ++nt) {
            const int row = m0 + wm + mt * 16 + lr;
            const int col = n0 + wn + nt * 8 + lc2;
            const float2 bv = *(const float2*)(bias + col);
            float v00 = acc[mt][nt][0] + bv.x, v01 = acc[mt][nt][1] + bv.y;
            float v10 = acc[mt][nt][2] + bv.x, v11 = acc[mt][nt][3] + bv.y;
            if (relu) {
                v00 = fmaxf(v00, 0.f); v01 = fmaxf(v01, 0.f);
                v10 = fmaxf(v10, 0.f); v11 = fmaxf(v11, 0.f);
            }
            const long o = (long)row * DIM + col;
            *(uint32_t*)(outH + o)            = pack2h(v00, v01);
            *(uint32_t*)(outH + o + 8L * DIM) = pack2h(v10, v11);
        }
    }
}

// ---------------------------------------------------------------------------
// Final GEMM: y[b] = q[b] @ MT[b]^T + o_b  (fp32 out)
// ---------------------------------------------------------------------------
__global__ __launch_bounds__(128, 3)
void gemm_out(const float* __restrict__ bias, float* __restrict__ outF)
{
    extern __shared__ char smem[];
    const uint32_t smem_addr = smem_u32(smem);

    const int tid = threadIdx.x;
    const int z   = blockIdx.z;
    const int m0  = blockIdx.y * TM;
    const int n0  = blockIdx.x * TN;

    const __half* A = g_q16 + (long)z * SEQ * DIM;
    const __half* B = g_mtf + (long)z * DIM * DIM;

    float acc[4][8][4] = {};
    gemm_mainloop(A, B, smem_addr, m0, n0, tid, acc);

    const int wid  = tid >> 5;
    const int lane = tid & 31;
    const int wm = (wid >> 1) * 64, wn = (wid & 1) * 64;
    const int lr = lane >> 2, lc2 = (lane & 3) * 2;

    float* out = outF + (long)z * SEQ * DIM;

    #pragma unroll
    for (int mt = 0; mt < 4; ++mt) {
        #pragma unroll
        for (int nt = 0; nt < 8; ++nt) {
            const int row = m0 + wm + mt * 16 + lr;
            const int col = n0 + wn + nt * 8 + lc2;
            const float2 bv = *(const float2*)(bias + col);
            float* p = out + (long)row * DIM + col;
            *(float2*)p              = make_float2(acc[mt][nt][0] + bv.x, acc[mt][nt][1] + bv.y);
            *(float2*)(p + 8L * DIM) = make_float2(acc[mt][nt][2] + bv.x, acc[mt][nt][3] + bv.y);
        }
    }
}

// ---------------------------------------------------------------------------
// kv partials on tensor cores: P[b,h,c,d,e] = sum_{s in chunk} k[s,d]*v[s,e].
// ---------------------------------------------------------------------------
__global__ __launch_bounds__(128)
void kv_mma()
{
    __shared__ __align__(16) char kvsm[2 * 2 * KVTILE];  // [buf][k/v][tile]

    const int c = blockIdx.x, hh = blockIdx.y, b = blockIdx.z;
    const int tid  = threadIdx.x;
    const int wid  = tid >> 5;
    const int lane = tid & 31;
    const uint32_t sbase = smem_u32(kvsm);

    const __half* kb = g_k16 + (long)(b * SEQ + c * SCH) * DIM + hh * HD;
    const __half* vb = g_v16 + (long)(b * SEQ + c * SCH) * DIM + hh * HD;

    uint32_t so[4];
    long go[4];
    #pragma unroll
    for (int i = 0; i < 4; ++i) {
        int idx = i * 128 + tid;
        int row = idx >> 3, ck = idx & 7;
        so[i] = (uint32_t)(row * RSK + ck * 8) * 2;
        go[i] = (long)row * DIM + ck * 8;
    }

    auto load_blk = [&](int blk, int buf) {
        const uint32_t sb = sbase + buf * 2 * KVTILE;
        const long ko = (long)blk * 64 * DIM;
        #pragma unroll
        for (int i = 0; i < 4; ++i) CP_ASYNC16(sb + so[i],          kb + ko + go[i]);
        #pragma unroll
        for (int i = 0; i < 4; ++i) CP_ASYNC16(sb + KVTILE + so[i], vb + ko + go[i]);
    };

    load_blk(0, 0); CP_COMMIT();

    const uint32_t rKA = (lane & 7) + ((lane & 16) >> 1);
    const uint32_t mAp = (lane & 8) << 1;
    const uint32_t rVB = lane & 15;
    const uint32_t nBp = (uint32_t)(lane >> 4) << 4;

    const int wn = wid * 16;   // e-range per warp

    float acc[4][2][4] = {};

    for (int blk = 0; blk < SCH / 64; ++blk) {
        if (blk + 1 < SCH / 64) load_blk(blk + 1, (blk + 1) & 1);
        CP_COMMIT();
        if (blk + 1 < SCH / 64) { CP_WAIT1(); } else { CP_WAIT0(); }
        __syncthreads();

        const uint32_t Sk = sbase + (blk & 1) * 2 * KVTILE;
        const uint32_t Sv = Sk + KVTILE;

        #pragma unroll
        for (int ks = 0; ks < 4; ++ks) {
            const uint32_t srow = ks * 16;
            uint32_t af[4][4], bf[2][2];

            #pragma unroll
            for (int mt = 0; mt < 4; ++mt) {
                const uint32_t aa = Sk + (srow + rKA) * (RSK * 2) + mt * 32 + mAp;
                LDSM_X4_T(af[mt][0], af[mt][1], af[mt][2], af[mt][3], aa);
            }
            {
                const uint32_t ba = Sv + (srow + rVB) * (RSK * 2) + wn * 2 + nBp;
                LDSM_X4_T(bf[0][0], bf[0][1], bf[1][0], bf[1][1], ba);
            }

            #pragma unroll
            for (int mt = 0; mt < 4; ++mt)
                #pragma unroll
                for (int nt = 0; nt < 2; ++nt)
                    mma16816(acc[mt][nt], af[mt], bf[nt]);
        }
        __syncthreads();
    }

    const int lr = lane >> 2, lc2 = (lane & 3) * 2;
    float* out = g_kvp + ((long)((b * NH + hh) * KVC + c)) * HD * HD;
    #pragma unroll
    for (int mt = 0; mt < 4; ++mt) {
        #pragma unroll
        for (int nt = 0; nt < 2; ++nt) {
            const int d = mt * 16 + lr;
            const int e = wn + nt * 8 + lc2;
            *(float2*)(out + (long)d * HD + e)       = make_float2(acc[mt][nt][0], acc[mt][nt][1]);
            *(float2*)(out + (long)(d + 8) * HD + e) = make_float2(acc[mt][nt][2], acc[mt][nt][3]);
        }
    }
}

// ---------------------------------------------------------------------------
// MT[b, j, h*64+d] = sum_e kv[b,h,d,e] * o_w[j, h*64+e]; output rounded fp16
// ---------------------------------------------------------------------------
__global__ __launch_bounds__(256)
void make_mt(const float* __restrict__ OW)
{
    __shared__ float kvs[64][65];
    __shared__ float ows[64][64];

    const int jt = blockIdx.x, hh = blockIdx.y, b = blockIdx.z;
    const int t  = threadIdx.x;
    const int j0 = jt * 64;

    const float* pb = g_kvp + (long)((b * NH + hh) * KVC) * HD * HD;
    #pragma unroll
    for (int r = 0; r < 16; ++r) {
        int idx = t + 256 * r;
        float s = 0.0f;
        #pragma unroll
        for (int c = 0; c < KVC; ++c) s += pb[c * HD * HD + idx];
        kvs[idx >> 6][idx & 63] = s;
    }
    #pragma unroll
    for (int r = 0; r < 16; ++r) {
        int idx = t + 256 * r;
        int row = idx >> 6, e = idx & 63;
        ows[row][e] = OW[(long)(j0 + row) * DIM + hh * HD + e];
    }
    __syncthreads();

    const int d  = t & 63;
    const int rb = (t >> 6) * 16;
    float acc[16] = {};

    #pragma unroll 4
    for (int e = 0; e < 64; ++e) {
        float kd = kvs[d][e];
        #pragma unroll
        for (int jj = 0; jj < 16; ++jj)
            acc[jj] += ows[rb + jj][e] * kd;
    }

    long base = (long)b * DIM * DIM + hh * HD + d;
    #pragma unroll
    for (int jj = 0; jj < 16; ++jj)
        g_mtf[base + (long)(j0 + rb + jj) * DIM] = __float2half_rn(acc[jj]);
}

// ---------------------------------------------------------------------------
// Launch
// ---------------------------------------------------------------------------
template <typename T>
static T* sym_addr(const void* sym) {
    void* p = nullptr;
    cudaGetSymbolAddress(&p, sym);
    return (T*)p;
}

extern "C" void kernel_launch(void* const* d_in, const int* in_sizes, int n_in,
                              void* d_out, int out_size)
{
    (void)in_sizes; (void)n_in; (void)out_size;
    const float* x  = (const float*)d_in[0];
    const float* qw = (const float*)d_in[1];
    const float* qb = (const float*)d_in[2];
    const float* kw = (const float*)d_in[3];
    const float* kb = (const float*)d_in[4];
    const float* vw = (const float*)d_in[5];
    const float* vb = (const float*)d_in[6];
    const float* ow = (const float*)d_in[7];
    const float* ob = (const float*)d_in[8];
    float* y = (float*)d_out;

    __half* x16  = sym_addr<__half>(g_x16);
    __half* qw16 = sym_addr<__half>(g_qw16);
    __half* kw16 = sym_addr<__half>(g_kw16);
    __half* vw16 = sym_addr<__half>(g_vw16);

    cudaFuncSetAttribute(gemm_qkv, cudaFuncAttributeMaxDynamicSharedMemorySize, GSMEM);
    cudaFuncSetAttribute(gemm_out, cudaFuncAttributeMaxDynamicSharedMemorySize, GSMEM);

    const long NX = (long)BATCH * SEQ * DIM;   // 16.7M
    const long NW = (long)DIM * DIM;           // 1M

    // 0) round x and weights to fp16
    round_f32h<<<(int)(NX / 4 / 256), 256>>>(x, x16, NX);
    round_w3<<<dim3((int)(NW / 4 / 256), 3, 1), 256>>>(qw, kw, vw, qw16, kw16, vw16, NW);

    // 1) fused QKV projections (z selects q/k/v)
    gemm_qkv<<<dim3(DIM / TN, (BATCH * SEQ) / TM, 3), 128, GSMEM>>>(qb, kb, vb);

    // 2) kv state partials on tensor cores
    kv_mma<<<dim3(KVC, NH, BATCH), 128>>>();

    // 3) fold o_w into kv state, round to fp16
    make_mt<<<dim3(DIM / 64, NH, BATCH), 256>>>(ow);

    // 4) y[b] = q[b] @ MT[b]^T + o_b
    gemm_out<<<dim3(DIM / TN, SEQ / TM, BATCH), 128, GSMEM>>>(ob, y);
}

// round 12
// speedup vs baseline: 1.1577x; 1.1577x over previous
#include <cuda_runtime.h>
#include <cuda_fp16.h>
#include <cstdint>

// Problem constants
#define BATCH 4
#define SEQ   4096
#define DIM   1024
#define NH    16
#define HD    64
#define KVC   8               // split-S chunks for kv accumulation
#define SCH   (SEQ / KVC)     // 512

// GEMM tile config (proven R9 configuration)
#define GK      1024
#define TM      128
#define TN      128
#define BK      32                   // K elements per chunk
#define NCHUNK  (GK / BK)            // 32
#define RS      40                   // smem row stride in fp16 (32 data + 8 pad) = 80B
#define TILE_B  (128 * RS * 2)       // 10240 bytes per tile
#define STAGE_B (2 * TILE_B)         // A, B = 20480 bytes
#define NSTAGE  4
#define GSMEM   (NSTAGE * STAGE_B)   // 81920 bytes -> 2 CTAs/SM

// kv tile config
#define RSK     72                   // kv smem row stride halves (64 + 8 pad) = 144B
#define KVTILE  (64 * RSK * 2)       // 9216 bytes

// ---------------------------------------------------------------------------
// Scratch
// ---------------------------------------------------------------------------
__device__ __half g_x16[BATCH * SEQ * DIM];
__device__ __half g_qw16[DIM * DIM], g_kw16[DIM * DIM], g_vw16[DIM * DIM];
__device__ __half g_q16[BATCH * SEQ * DIM];
__device__ __half g_k16[BATCH * SEQ * DIM];
__device__ __half g_v16[BATCH * SEQ * DIM];
__device__ float g_kvp[BATCH * NH * KVC * HD * HD];
__device__ __half g_mtf[BATCH * DIM * DIM];

// ---------------------------------------------------------------------------
// PTX helpers
// ---------------------------------------------------------------------------
__device__ __forceinline__ uint32_t smem_u32(const void* p) {
    uint32_t a;
    asm("{ .reg .u64 t; cvta.to.shared.u64 t, %1; cvt.u32.u64 %0, t; }" : "=r"(a) : "l"(p));
    return a;
}

#define CP_ASYNC16(s, g) asm volatile("cp.async.cg.shared.global [%0], [%1], 16;" :: "r"(s), "l"(g))
#define CP_COMMIT()      asm volatile("cp.async.commit_group;" ::: "memory")
#define CP_WAIT2()       asm volatile("cp.async.wait_group 2;" ::: "memory")
#define CP_WAIT1()       asm volatile("cp.async.wait_group 1;" ::: "memory")
#define CP_WAIT0()       asm volatile("cp.async.wait_group 0;" ::: "memory")

#define LDSM_X4(r0, r1, r2, r3, a) \
    asm volatile("ldmatrix.sync.aligned.m8n8.x4.shared.b16 {%0,%1,%2,%3}, [%4];" \
                 : "=r"(r0), "=r"(r1), "=r"(r2), "=r"(r3) : "r"(a))
#define LDSM_X4_T(r0, r1, r2, r3, a) \
    asm volatile("ldmatrix.sync.aligned.m8n8.x4.trans.shared.b16 {%0,%1,%2,%3}, [%4];" \
                 : "=r"(r0), "=r"(r1), "=r"(r2), "=r"(r3) : "r"(a))

// D += A * B  (m16n8k16, fp16 in, f32 accum)
__device__ __forceinline__ void mma16816(float* c, const uint32_t* a, const uint32_t* b) {
    asm volatile(
        "mma.sync.aligned.m16n8k16.row.col.f32.f16.f16.f32 "
        "{%0,%1,%2,%3}, {%4,%5,%6,%7}, {%8,%9}, {%0,%1,%2,%3};"
        : "+f"(c[0]), "+f"(c[1]), "+f"(c[2]), "+f"(c[3])
        : "r"(a[0]), "r"(a[1]), "r"(a[2]), "r"(a[3]), "r"(b[0]), "r"(b[1]));
}

__device__ __forceinline__ uint32_t pack2h(float lo_v, float hi_v) {
    uint32_t r;
    asm("cvt.rn.f16x2.f32 %0, %1, %2;" : "=r"(r) : "f"(hi_v), "f"(lo_v));
    return r;
}

// ---------------------------------------------------------------------------
// Merged rounding kernel: fp32 -> fp16 for x (16384 blocks) + qw/kw/vw (1024 each)
// ---------------------------------------------------------------------------
#define XBLK 16384
#define WBLK 1024
__global__ void round_all(const float* __restrict__ x,
                          const float* __restrict__ qw, const float* __restrict__ kw,
                          const float* __restrict__ vw)
{
    int bid = blockIdx.x;
    const float* s;
    __half* o;
    long base;
    if (bid < XBLK) {
        s = x; o = g_x16; base = (long)bid * 1024;
    } else if (bid < XBLK + WBLK) {
        s = qw; o = g_qw16; base = (long)(bid - XBLK) * 1024;
    } else if (bid < XBLK + 2 * WBLK) {
        s = kw; o = g_kw16; base = (long)(bid - XBLK - WBLK) * 1024;
    } else {
        s = vw; o = g_vw16; base = (long)(bid - XBLK - 2 * WBLK) * 1024;
    }
    long i = base + (long)threadIdx.x * 4;
    float4 v = *(const float4*)(s + i);
    *(uint2*)(o + i) = make_uint2(pack2h(v.x, v.y), pack2h(v.z, v.w));
}

// ---------------------------------------------------------------------------
// Shared GEMM mainloop (R9-proven): 128 threads, 4 warps (2x2), warp tile 64x64.
// acc[4][8][4] += A_tile[m0:128,:] * B_tile[n0:128,:]^T. BK=32, 4-stage ring.
// ---------------------------------------------------------------------------
__device__ __forceinline__ void gemm_mainloop(
    const __half* __restrict__ A, const __half* __restrict__ B,
    uint32_t smem_addr, int m0, int n0, int tid, float acc[4][8][4])
{
    const int wid  = tid >> 5;
    const int lane = tid & 31;

    // cp.async geometry: tile = 128 rows x 4 (16B chunks); 4 slots/thread/tile
    uint32_t so[4];
    long ga[4], gb[4];
    #pragma unroll
    for (int i = 0; i < 4; ++i) {
        int idx = i * 128 + tid;
        int row = idx >> 2, ck = idx & 3;
        so[i] = (uint32_t)(row * RS + ck * 8) * 2;
        ga[i] = (long)(m0 + row) * GK + ck * 8;
        gb[i] = (long)(n0 + row) * GK + ck * 8;
    }

    auto load_stage = [&](int kt, int buf) {
        const uint32_t sb = smem_addr + buf * STAGE_B;
        const long ko = (long)kt * BK;
        #pragma unroll
        for (int i = 0; i < 4; ++i) CP_ASYNC16(sb + so[i],          A + ga[i] + ko);
        #pragma unroll
        for (int i = 0; i < 4; ++i) CP_ASYNC16(sb + TILE_B + so[i], B + gb[i] + ko);
    };

    load_stage(0, 0); CP_COMMIT();
    load_stage(1, 1); CP_COMMIT();
    load_stage(2, 2); CP_COMMIT();

    // Warp tiling: 2x2 warp grid, each warp 64x64
    const int wm = (wid >> 1) * 64;
    const int wn = (wid & 1) * 64;

    // ldmatrix per-lane address parts
    const uint32_t rA  = lane & 15;
    const uint32_t kAp = (uint32_t)(lane >> 4) << 4;
    const uint32_t rB  = (lane & 7) + ((lane & 16) >> 1);
    const uint32_t kBp = (lane & 8) << 1;

    uint32_t offA[4], offB[4];
    #pragma unroll
    for (int mt = 0; mt < 4; ++mt)
        offA[mt] = (uint32_t)(wm + mt * 16 + rA) * (RS * 2) + kAp;
    #pragma unroll
    for (int ntp = 0; ntp < 4; ++ntp)
        offB[ntp] = (uint32_t)(wn + ntp * 16 + rB) * (RS * 2) + kBp;

    for (int kt = 0; kt < NCHUNK; ++kt) {
        CP_WAIT2();
        __syncthreads();

        if (kt + 3 < NCHUNK) load_stage(kt + 3, (kt + 3) & 3);
        CP_COMMIT();

        const uint32_t Sb = smem_addr + (kt & 3) * STAGE_B;

        #pragma unroll
        for (int ks2 = 0; ks2 < 2; ++ks2) {
            const uint32_t kb = ks2 * 32;   // 16 k-elements = 32 bytes
            uint32_t af[4][4], bf[8][2];

            #pragma unroll
            for (int mt = 0; mt < 4; ++mt)
                LDSM_X4(af[mt][0], af[mt][1], af[mt][2], af[mt][3], Sb + kb + offA[mt]);
            #pragma unroll
            for (int ntp = 0; ntp < 4; ++ntp) {
                const uint32_t ba = Sb + TILE_B + kb + offB[ntp];
                LDSM_X4(bf[2*ntp][0], bf[2*ntp][1], bf[2*ntp+1][0], bf[2*ntp+1][1], ba);
            }

            #pragma unroll
            for (int mt = 0; mt < 4; ++mt)
                #pragma unroll
                for (int nt = 0; nt < 8; ++nt)
                    mma16816(acc[mt][nt], af[mt], bf[nt]);
        }
    }
}

// ---------------------------------------------------------------------------
// Fused QKV GEMM: blockIdx.z selects (W, bias, out, relu). fp16 out.
// ---------------------------------------------------------------------------
__global__ __launch_bounds__(128, 2)
void gemm_qkv(const float* __restrict__ qb, const float* __restrict__ kb,
              const float* __restrict__ vb)
{
    extern __shared__ char smem[];
    const uint32_t smem_addr = smem_u32(smem);

    const int tid = threadIdx.x;
    const int z   = blockIdx.z;
    const int m0  = blockIdx.y * TM;
    const int n0  = blockIdx.x * TN;

    const __half* B    = (z == 0) ? g_qw16 : (z == 1) ? g_kw16 : g_vw16;
    const float*  bias = (z == 0) ? qb     : (z == 1) ? kb     : vb;
    __half*       outH = (z == 0) ? g_q16  : (z == 1) ? g_k16  : g_v16;
    const bool    relu = (z != 2);

    float acc[4][8][4] = {};
    gemm_mainloop(g_x16, B, smem_addr, m0, n0, tid, acc);

    const int wid  = tid >> 5;
    const int lane = tid & 31;
    const int wm = (wid >> 1) * 64, wn = (wid & 1) * 64;
    const int lr = lane >> 2, lc2 = (lane & 3) * 2;

    #pragma unroll
    for (int mt = 0; mt < 4; ++mt) {
        #pragma unroll
        for (int nt = 0; nt < 8; ++nt) {
            const int row = m0 + wm + mt * 16 + lr;
            const int col = n0 + wn + nt * 8 + lc2;
            const float2 bv = *(const float2*)(bias + col);
            float v00 = acc[mt][nt][0] + bv.x, v01 = acc[mt][nt][1] + bv.y;
            float v10 = acc[mt][nt][2] + bv.x, v11 = acc[mt][nt][3] + bv.y;
            if (relu) {
                v00 = fmaxf(v00, 0.f); v01 = fmaxf(v01, 0.f);
                v10 = fmaxf(v10, 0.f); v11 = fmaxf(v11, 0.f);
            }
            const long o = (long)row * DIM + col;
            *(uint32_t*)(outH + o)            = pack2h(v00, v01);
            *(uint32_t*)(outH + o + 8L * DIM) = pack2h(v10, v11);
        }
    }
}

// ---------------------------------------------------------------------------
// Final GEMM: y[b] = q[b] @ MT[b]^T + o_b  (fp32 out)
// ---------------------------------------------------------------------------
__global__ __launch_bounds__(128, 2)
void gemm_out(const float* __restrict__ bias, float* __restrict__ outF)
{
    extern __shared__ char smem[];
    const uint32_t smem_addr = smem_u32(smem);

    const int tid = threadIdx.x;
    const int z   = blockIdx.z;
    const int m0  = blockIdx.y * TM;
    const int n0  = blockIdx.x * TN;

    const __half* A = g_q16 + (long)z * SEQ * DIM;
    const __half* B = g_mtf + (long)z * DIM * DIM;

    float acc[4][8][4] = {};
    gemm_mainloop(A, B, smem_addr, m0, n0, tid, acc);

    const int wid  = tid >> 5;
    const int lane = tid & 31;
    const int wm = (wid >> 1) * 64, wn = (wid & 1) * 64;
    const int lr = lane >> 2, lc2 = (lane & 3) * 2;

    float* out = outF + (long)z * SEQ * DIM;

    #pragma unroll
    for (int mt = 0; mt < 4; ++mt) {
        #pragma unroll
        for (int nt = 0; nt < 8; ++nt) {
            const int row = m0 + wm + mt * 16 + lr;
            const int col = n0 + wn + nt * 8 + lc2;
            const float2 bv = *(const float2*)(bias + col);
            float* p = out + (long)row * DIM + col;
            *(float2*)p              = make_float2(acc[mt][nt][0] + bv.x, acc[mt][nt][1] + bv.y);
            *(float2*)(p + 8L * DIM) = make_float2(acc[mt][nt][2] + bv.x, acc[mt][nt][3] + bv.y);
        }
    }
}

// ---------------------------------------------------------------------------
// kv partials on tensor cores: P[b,h,c,d,e] = sum_{s in chunk} k[s,d]*v[s,e].
// ---------------------------------------------------------------------------
__global__ __launch_bounds__(128)
void kv_mma()
{
    __shared__ __align__(16) char kvsm[2 * 2 * KVTILE];  // [buf][k/v][tile]

    const int c = blockIdx.x, hh = blockIdx.y, b = blockIdx.z;
    const int tid  = threadIdx.x;
    const int wid  = tid >> 5;
    const int lane = tid & 31;
    const uint32_t sbase = smem_u32(kvsm);

    const __half* kb = g_k16 + (long)(b * SEQ + c * SCH) * DIM + hh * HD;
    const __half* vb = g_v16 + (long)(b * SEQ + c * SCH) * DIM + hh * HD;

    uint32_t so[4];
    long go[4];
    #pragma unroll
    for (int i = 0; i < 4; ++i) {
        int idx = i * 128 + tid;
        int row = idx >> 3, ck = idx & 7;
        so[i] = (uint32_t)(row * RSK + ck * 8) * 2;
        go[i] = (long)row * DIM + ck * 8;
    }

    auto load_blk = [&](int blk, int buf) {
        const uint32_t sb = sbase + buf * 2 * KVTILE;
        const long ko = (long)blk * 64 * DIM;
        #pragma unroll
        for (int i = 0; i < 4; ++i) CP_ASYNC16(sb + so[i],          kb + ko + go[i]);
        #pragma unroll
        for (int i = 0; i < 4; ++i) CP_ASYNC16(sb + KVTILE + so[i], vb + ko + go[i]);
    };

    load_blk(0, 0); CP_COMMIT();

    const uint32_t rKA = (lane & 7) + ((lane & 16) >> 1);
    const uint32_t mAp = (lane & 8) << 1;
    const uint32_t rVB = lane & 15;
    const uint32_t nBp = (uint32_t)(lane >> 4) << 4;

    const int wn = wid * 16;   // e-range per warp

    float acc[4][2][4] = {};

    for (int blk = 0; blk < SCH / 64; ++blk) {
        if (blk + 1 < SCH / 64) load_blk(blk + 1, (blk + 1) & 1);
        CP_COMMIT();
        if (blk + 1 < SCH / 64) { CP_WAIT1(); } else { CP_WAIT0(); }
        __syncthreads();

        const uint32_t Sk = sbase + (blk & 1) * 2 * KVTILE;
        const uint32_t Sv = Sk + KVTILE;

        #pragma unroll
        for (int ks = 0; ks < 4; ++ks) {
            const uint32_t srow = ks * 16;
            uint32_t af[4][4], bf[2][2];

            #pragma unroll
            for (int mt = 0; mt < 4; ++mt) {
                const uint32_t aa = Sk + (srow + rKA) * (RSK * 2) + mt * 32 + mAp;
                LDSM_X4_T(af[mt][0], af[mt][1], af[mt][2], af[mt][3], aa);
            }
            {
                const uint32_t ba = Sv + (srow + rVB) * (RSK * 2) + wn * 2 + nBp;
                LDSM_X4_T(bf[0][0], bf[0][1], bf[1][0], bf[1][1], ba);
            }

            #pragma unroll
            for (int mt = 0; mt < 4; ++mt)
                #pragma unroll
                for (int nt = 0; nt < 2; ++nt)
                    mma16816(acc[mt][nt], af[mt], bf[nt]);
        }
        __syncthreads();
    }

    const int lr = lane >> 2, lc2 = (lane & 3) * 2;
    float* out = g_kvp + ((long)((b * NH + hh) * KVC + c)) * HD * HD;
    #pragma unroll
    for (int mt = 0; mt < 4; ++mt) {
        #pragma unroll
        for (int nt = 0; nt < 2; ++nt) {
            const int d = mt * 16 + lr;
            const int e = wn + nt * 8 + lc2;
            *(float2*)(out + (long)d * HD + e)       = make_float2(acc[mt][nt][0], acc[mt][nt][1]);
            *(float2*)(out + (long)(d + 8) * HD + e) = make_float2(acc[mt][nt][2], acc[mt][nt][3]);
        }
    }
}

// ---------------------------------------------------------------------------
// MT[b, j, h*64+d] = sum_e kv[b,h,d,e] * o_w[j, h*64+e]; output rounded fp16
// ---------------------------------------------------------------------------
__global__ __launch_bounds__(256)
void make_mt(const float* __restrict__ OW)
{
    __shared__ float kvs[64][65];
    __shared__ float ows[64][64];

    const int jt = blockIdx.x, hh = blockIdx.y, b = blockIdx.z;
    const int t  = threadIdx.x;
    const int j0 = jt * 64;

    const float* pb = g_kvp + (long)((b * NH + hh) * KVC) * HD * HD;
    #pragma unroll
    for (int r = 0; r < 16; ++r) {
        int idx = t + 256 * r;
        float s = 0.0f;
        #pragma unroll
        for (int c = 0; c < KVC; ++c) s += pb[c * HD * HD + idx];
        kvs[idx >> 6][idx & 63] = s;
    }
    #pragma unroll
    for (int r = 0; r < 16; ++r) {
        int idx = t + 256 * r;
        int row = idx >> 6, e = idx & 63;
        ows[row][e] = OW[(long)(j0 + row) * DIM + hh * HD + e];
    }
    __syncthreads();

    const int d  = t & 63;
    const int rb = (t >> 6) * 16;
    float acc[16] = {};

    #pragma unroll 4
    for (int e = 0; e < 64; ++e) {
        float kd = kvs[d][e];
        #pragma unroll
        for (int jj = 0; jj < 16; ++jj)
            acc[jj] += ows[rb + jj][e] * kd;
    }

    long base = (long)b * DIM * DIM + hh * HD + d;
    #pragma unroll
    for (int jj = 0; jj < 16; ++jj)
        g_mtf[base + (long)(j0 + rb + jj) * DIM] = __float2half_rn(acc[jj]);
}

// ---------------------------------------------------------------------------
// Launch
// ---------------------------------------------------------------------------
extern "C" void kernel_launch(void* const* d_in, const int* in_sizes, int n_in,
                              void* d_out, int out_size)
{
    (void)in_sizes; (void)n_in; (void)out_size;
    const float* x  = (const float*)d_in[0];
    const float* qw = (const float*)d_in[1];
    const float* qb = (const float*)d_in[2];
    const float* kw = (const float*)d_in[3];
    const float* kb = (const float*)d_in[4];
    const float* vw = (const float*)d_in[5];
    const float* vb = (const float*)d_in[6];
    const float* ow = (const float*)d_in[7];
    const float* ob = (const float*)d_in[8];
    float* y = (float*)d_out;

    cudaFuncSetAttribute(gemm_qkv, cudaFuncAttributeMaxDynamicSharedMemorySize, GSMEM);
    cudaFuncSetAttribute(gemm_out, cudaFuncAttributeMaxDynamicSharedMemorySize, GSMEM);

    // 0) round x and all three weight matrices to fp16 in one launch
    round_all<<<XBLK + 3 * WBLK, 256>>>(x, qw, kw, vw);

    // 1) fused QKV projections (z selects q/k/v)
    gemm_qkv<<<dim3(DIM / TN, (BATCH * SEQ) / TM, 3), 128, GSMEM>>>(qb, kb, vb);

    // 2) kv state partials on tensor cores
    kv_mma<<<dim3(KVC, NH, BATCH), 128>>>();

    // 3) fold o_w into kv state, round to fp16
    make_mt<<<dim3(DIM / 64, NH, BATCH), 256>>>(ow);

    // 4) y[b] = q[b] @ MT[b]^T + o_b
    gemm_out<<<dim3(DIM / TN, SEQ / TM, BATCH), 128, GSMEM>>>(ob, y);
}

// round 13
// speedup vs baseline: 1.1926x; 1.0301x over previous
#include <cuda_runtime.h>
#include <cuda_fp16.h>
#include <cstdint>

// Problem constants
#define BATCH 4
#define SEQ   4096
#define DIM   1024
#define NH    16
#define HD    64
#define KVC   8               // split-S chunks for kv accumulation
#define SCH   (SEQ / KVC)     // 512

// GEMM tile config (proven R9 configuration — FROZEN)
#define GK      1024
#define TM      128
#define TN      128
#define BK      32                   // K elements per chunk
#define NCHUNK  (GK / BK)            // 32
#define RS      40                   // smem row stride in fp16 (32 data + 8 pad) = 80B
#define TILE_B  (128 * RS * 2)       // 10240 bytes per tile
#define STAGE_B (2 * TILE_B)         // A, B = 20480 bytes
#define NSTAGE  4
#define GSMEM   (NSTAGE * STAGE_B)   // 81920 bytes -> 2 CTAs/SM

// kv tile config
#define RSK     72                   // kv smem row stride halves (64 + 8 pad) = 144B
#define KVTILE  (64 * RSK * 2)       // 9216 bytes

// ---------------------------------------------------------------------------
// Scratch
// ---------------------------------------------------------------------------
__device__ __half g_x16[BATCH * SEQ * DIM];
__device__ __half g_qw16[DIM * DIM], g_kw16[DIM * DIM], g_vw16[DIM * DIM];
__device__ __half g_q16[BATCH * SEQ * DIM];
__device__ __half g_k16[BATCH * SEQ * DIM];
__device__ __half g_v16[BATCH * SEQ * DIM];
__device__ float  g_kvp[BATCH * NH * KVC * HD * HD];
__device__ __half g_kv16[BATCH * NH * HD * HD];
__device__ __half g_mtf[BATCH * DIM * DIM];

// ---------------------------------------------------------------------------
// PTX helpers
// ---------------------------------------------------------------------------
__device__ __forceinline__ uint32_t smem_u32(const void* p) {
    uint32_t a;
    asm("{ .reg .u64 t; cvta.to.shared.u64 t, %1; cvt.u32.u64 %0, t; }" : "=r"(a) : "l"(p));
    return a;
}

#define CP_ASYNC16(s, g) asm volatile("cp.async.cg.shared.global [%0], [%1], 16;" :: "r"(s), "l"(g))
#define CP_COMMIT()      asm volatile("cp.async.commit_group;" ::: "memory")
#define CP_WAIT2()       asm volatile("cp.async.wait_group 2;" ::: "memory")
#define CP_WAIT1()       asm volatile("cp.async.wait_group 1;" ::: "memory")
#define CP_WAIT0()       asm volatile("cp.async.wait_group 0;" ::: "memory")

#define LDSM_X4(r0, r1, r2, r3, a) \
    asm volatile("ldmatrix.sync.aligned.m8n8.x4.shared.b16 {%0,%1,%2,%3}, [%4];" \
                 : "=r"(r0), "=r"(r1), "=r"(r2), "=r"(r3) : "r"(a))
#define LDSM_X4_T(r0, r1, r2, r3, a) \
    asm volatile("ldmatrix.sync.aligned.m8n8.x4.trans.shared.b16 {%0,%1,%2,%3}, [%4];" \
                 : "=r"(r0), "=r"(r1), "=r"(r2), "=r"(r3) : "r"(a))

// D += A * B  (m16n8k16, fp16 in, f32 accum)
__device__ __forceinline__ void mma16816(float* c, const uint32_t* a, const uint32_t* b) {
    asm volatile(
        "mma.sync.aligned.m16n8k16.row.col.f32.f16.f16.f32 "
        "{%0,%1,%2,%3}, {%4,%5,%6,%7}, {%8,%9}, {%0,%1,%2,%3};"
        : "+f"(c[0]), "+f"(c[1]), "+f"(c[2]), "+f"(c[3])
        : "r"(a[0]), "r"(a[1]), "r"(a[2]), "r"(a[3]), "r"(b[0]), "r"(b[1]));
}

__device__ __forceinline__ uint32_t pack2h(float lo_v, float hi_v) {
    uint32_t r;
    asm("cvt.rn.f16x2.f32 %0, %1, %2;" : "=r"(r) : "f"(hi_v), "f"(lo_v));
    return r;
}

// ---------------------------------------------------------------------------
// Merged rounding kernel: fp32 -> fp16 for x (16384 blocks) + qw/kw/vw (1024 each)
// ---------------------------------------------------------------------------
#define XBLK 16384
#define WBLK 1024
__global__ void round_all(const float* __restrict__ x,
                          const float* __restrict__ qw, const float* __restrict__ kw,
                          const float* __restrict__ vw)
{
    int bid = blockIdx.x;
    const float* s;
    __half* o;
    long base;
    if (bid < XBLK) {
        s = x; o = g_x16; base = (long)bid * 1024;
    } else if (bid < XBLK + WBLK) {
        s = qw; o = g_qw16; base = (long)(bid - XBLK) * 1024;
    } else if (bid < XBLK + 2 * WBLK) {
        s = kw; o = g_kw16; base = (long)(bid - XBLK - WBLK) * 1024;
    } else {
        s = vw; o = g_vw16; base = (long)(bid - XBLK - 2 * WBLK) * 1024;
    }
    long i = base + (long)threadIdx.x * 4;
    float4 v = *(const float4*)(s + i);
    *(uint2*)(o + i) = make_uint2(pack2h(v.x, v.y), pack2h(v.z, v.w));
}

// ---------------------------------------------------------------------------
// Shared GEMM mainloop (R9-proven, FROZEN): 128 threads, 4 warps (2x2),
// warp tile 64x64. acc[4][8][4] += A*B^T. BK=32, 4-stage ring.
// ---------------------------------------------------------------------------
__device__ __forceinline__ void gemm_mainloop(
    const __half* __restrict__ A, const __half* __restrict__ B,
    uint32_t smem_addr, int m0, int n0, int tid, float acc[4][8][4])
{
    const int wid  = tid >> 5;
    const int lane = tid & 31;

    uint32_t so[4];
    long ga[4], gb[4];
    #pragma unroll
    for (int i = 0; i < 4; ++i) {
        int idx = i * 128 + tid;
        int row = idx >> 2, ck = idx & 3;
        so[i] = (uint32_t)(row * RS + ck * 8) * 2;
        ga[i] = (long)(m0 + row) * GK + ck * 8;
        gb[i] = (long)(n0 + row) * GK + ck * 8;
    }

    auto load_stage = [&](int kt, int buf) {
        const uint32_t sb = smem_addr + buf * STAGE_B;
        const long ko = (long)kt * BK;
        #pragma unroll
        for (int i = 0; i < 4; ++i) CP_ASYNC16(sb + so[i],          A + ga[i] + ko);
        #pragma unroll
        for (int i = 0; i < 4; ++i) CP_ASYNC16(sb + TILE_B + so[i], B + gb[i] + ko);
    };

    load_stage(0, 0); CP_COMMIT();
    load_stage(1, 1); CP_COMMIT();
    load_stage(2, 2); CP_COMMIT();

    const int wm = (wid >> 1) * 64;
    const int wn = (wid & 1) * 64;

    const uint32_t rA  = lane & 15;
    const uint32_t kAp = (uint32_t)(lane >> 4) << 4;
    const uint32_t rB  = (lane & 7) + ((lane & 16) >> 1);
    const uint32_t kBp = (lane & 8) << 1;

    uint32_t offA[4], offB[4];
    #pragma unroll
    for (int mt = 0; mt < 4; ++mt)
        offA[mt] = (uint32_t)(wm + mt * 16 + rA) * (RS * 2) + kAp;
    #pragma unroll
    for (int ntp = 0; ntp < 4; ++ntp)
        offB[ntp] = (uint32_t)(wn + ntp * 16 + rB) * (RS * 2) + kBp;

    for (int kt = 0; kt < NCHUNK; ++kt) {
        CP_WAIT2();
        __syncthreads();

        if (kt + 3 < NCHUNK) load_stage(kt + 3, (kt + 3) & 3);
        CP_COMMIT();

        const uint32_t Sb = smem_addr + (kt & 3) * STAGE_B;

        #pragma unroll
        for (int ks2 = 0; ks2 < 2; ++ks2) {
            const uint32_t kb = ks2 * 32;
            uint32_t af[4][4], bf[8][2];

            #pragma unroll
            for (int mt = 0; mt < 4; ++mt)
                LDSM_X4(af[mt][0], af[mt][1], af[mt][2], af[mt][3], Sb + kb + offA[mt]);
            #pragma unroll
            for (int ntp = 0; ntp < 4; ++ntp) {
                const uint32_t ba = Sb + TILE_B + kb + offB[ntp];
                LDSM_X4(bf[2*ntp][0], bf[2*ntp][1], bf[2*ntp+1][0], bf[2*ntp+1][1], ba);
            }

            #pragma unroll
            for (int mt = 0; mt < 4; ++mt)
                #pragma unroll
                for (int nt = 0; nt < 8; ++nt)
                    mma16816(acc[mt][nt], af[mt], bf[nt]);
        }
    }
}

// ---------------------------------------------------------------------------
// Fused QKV GEMM: blockIdx.z selects (W, bias, out, relu). fp16 out.
// ---------------------------------------------------------------------------
__global__ __launch_bounds__(128, 2)
void gemm_qkv(const float* __restrict__ qb, const float* __restrict__ kb,
              const float* __restrict__ vb)
{
    extern __shared__ char smem[];
    const uint32_t smem_addr = smem_u32(smem);

    const int tid = threadIdx.x;
    const int z   = blockIdx.z;
    const int m0  = blockIdx.y * TM;
    const int n0  = blockIdx.x * TN;

    const __half* B    = (z == 0) ? g_qw16 : (z == 1) ? g_kw16 : g_vw16;
    const float*  bias = (z == 0) ? qb     : (z == 1) ? kb     : vb;
    __half*       outH = (z == 0) ? g_q16  : (z == 1) ? g_k16  : g_v16;
    const bool    relu = (z != 2);

    float acc[4][8][4] = {};
    gemm_mainloop(g_x16, B, smem_addr, m0, n0, tid, acc);

    const int wid  = tid >> 5;
    const int lane = tid & 31;
    const int wm = (wid >> 1) * 64, wn = (wid & 1) * 64;
    const int lr = lane >> 2, lc2 = (lane & 3) * 2;

    #pragma unroll
    for (int mt = 0; mt < 4; ++mt) {
        #pragma unroll
        for (int nt = 0; nt < 8; ++nt) {
            const int row = m0 + wm + mt * 16 + lr;
            const int col = n0 + wn + nt * 8 + lc2;
            const float2 bv = *(const float2*)(bias + col);
            float v00 = acc[mt][nt][0] + bv.x, v01 = acc[mt][nt][1] + bv.y;
            float v10 = acc[mt][nt][2] + bv.x, v11 = acc[mt][nt][3] + bv.y;
            if (relu) {
                v00 = fmaxf(v00, 0.f); v01 = fmaxf(v01, 0.f);
                v10 = fmaxf(v10, 0.f); v11 = fmaxf(v11, 0.f);
            }
            const long o = (long)row * DIM + col;
            *(uint32_t*)(outH + o)            = pack2h(v00, v01);
            *(uint32_t*)(outH + o + 8L * DIM) = pack2h(v10, v11);
        }
    }
}

// ---------------------------------------------------------------------------
// Final GEMM: y[b] = q[b] @ MT[b]^T + o_b  (fp32 out)
// ---------------------------------------------------------------------------
__global__ __launch_bounds__(128, 2)
void gemm_out(const float* __restrict__ bias, float* __restrict__ outF)
{
    extern __shared__ char smem[];
    const uint32_t smem_addr = smem_u32(smem);

    const int tid = threadIdx.x;
    const int z   = blockIdx.z;
    const int m0  = blockIdx.y * TM;
    const int n0  = blockIdx.x * TN;

    const __half* A = g_q16 + (long)z * SEQ * DIM;
    const __half* B = g_mtf + (long)z * DIM * DIM;

    float acc[4][8][4] = {};
    gemm_mainloop(A, B, smem_addr, m0, n0, tid, acc);

    const int wid  = tid >> 5;
    const int lane = tid & 31;
    const int wm = (wid >> 1) * 64, wn = (wid & 1) * 64;
    const int lr = lane >> 2, lc2 = (lane & 3) * 2;

    float* out = outF + (long)z * SEQ * DIM;

    #pragma unroll
    for (int mt = 0; mt < 4; ++mt) {
        #pragma unroll
        for (int nt = 0; nt < 8; ++nt) {
            const int row = m0 + wm + mt * 16 + lr;
            const int col = n0 + wn + nt * 8 + lc2;
            const float2 bv = *(const float2*)(bias + col);
            float* p = out + (long)row * DIM + col;
            *(float2*)p              = make_float2(acc[mt][nt][0] + bv.x, acc[mt][nt][1] + bv.y);
            *(float2*)(p + 8L * DIM) = make_float2(acc[mt][nt][2] + bv.x, acc[mt][nt][3] + bv.y);
        }
    }
}

// ---------------------------------------------------------------------------
// kv partials on tensor cores: P[b,h,c,d,e] = sum_{s in chunk} k[s,d]*v[s,e].
// ---------------------------------------------------------------------------
__global__ __launch_bounds__(128)
void kv_mma()
{
    __shared__ __align__(16) char kvsm[2 * 2 * KVTILE];  // [buf][k/v][tile]

    const int c = blockIdx.x, hh = blockIdx.y, b = blockIdx.z;
    const int tid  = threadIdx.x;
    const int wid  = tid >> 5;
    const int lane = tid & 31;
    const uint32_t sbase = smem_u32(kvsm);

    const __half* kb = g_k16 + (long)(b * SEQ + c * SCH) * DIM + hh * HD;
    const __half* vb = g_v16 + (long)(b * SEQ + c * SCH) * DIM + hh * HD;

    uint32_t so[4];
    long go[4];
    #pragma unroll
    for (int i = 0; i < 4; ++i) {
        int idx = i * 128 + tid;
        int row = idx >> 3, ck = idx & 7;
        so[i] = (uint32_t)(row * RSK + ck * 8) * 2;
        go[i] = (long)row * DIM + ck * 8;
    }

    auto load_blk = [&](int blk, int buf) {
        const uint32_t sb = sbase + buf * 2 * KVTILE;
        const long ko = (long)blk * 64 * DIM;
        #pragma unroll
        for (int i = 0; i < 4; ++i) CP_ASYNC16(sb + so[i],          kb + ko + go[i]);
        #pragma unroll
        for (int i = 0; i < 4; ++i) CP_ASYNC16(sb + KVTILE + so[i], vb + ko + go[i]);
    };

    load_blk(0, 0); CP_COMMIT();

    const uint32_t rKA = (lane & 7) + ((lane & 16) >> 1);
    const uint32_t mAp = (lane & 8) << 1;
    const uint32_t rVB = lane & 15;
    const uint32_t nBp = (uint32_t)(lane >> 4) << 4;

    const int wn = wid * 16;   // e-range per warp

    float acc[4][2][4] = {};

    for (int blk = 0; blk < SCH / 64; ++blk) {
        if (blk + 1 < SCH / 64) load_blk(blk + 1, (blk + 1) & 1);
        CP_COMMIT();
        if (blk + 1 < SCH / 64) { CP_WAIT1(); } else { CP_WAIT0(); }
        __syncthreads();

        const uint32_t Sk = sbase + (blk & 1) * 2 * KVTILE;
        const uint32_t Sv = Sk + KVTILE;

        #pragma unroll
        for (int ks = 0; ks < 4; ++ks) {
            const uint32_t srow = ks * 16;
            uint32_t af[4][4], bf[2][2];

            #pragma unroll
            for (int mt = 0; mt < 4; ++mt) {
                const uint32_t aa = Sk + (srow + rKA) * (RSK * 2) + mt * 32 + mAp;
                LDSM_X4_T(af[mt][0], af[mt][1], af[mt][2], af[mt][3], aa);
            }
            {
                const uint32_t ba = Sv + (srow + rVB) * (RSK * 2) + wn * 2 + nBp;
                LDSM_X4_T(bf[0][0], bf[0][1], bf[1][0], bf[1][1], ba);
            }

            #pragma unroll
            for (int mt = 0; mt < 4; ++mt)
                #pragma unroll
                for (int nt = 0; nt < 2; ++nt)
                    mma16816(acc[mt][nt], af[mt], bf[nt]);
        }
        __syncthreads();
    }

    const int lr = lane >> 2, lc2 = (lane & 3) * 2;
    float* out = g_kvp + ((long)((b * NH + hh) * KVC + c)) * HD * HD;
    #pragma unroll
    for (int mt = 0; mt < 4; ++mt) {
        #pragma unroll
        for (int nt = 0; nt < 2; ++nt) {
            const int d = mt * 16 + lr;
            const int e = wn + nt * 8 + lc2;
            *(float2*)(out + (long)d * HD + e)       = make_float2(acc[mt][nt][0], acc[mt][nt][1]);
            *(float2*)(out + (long)(d + 8) * HD + e) = make_float2(acc[mt][nt][2], acc[mt][nt][3]);
        }
    }
}

// ---------------------------------------------------------------------------
// kv_sum: sum the KVC fp32 partials per (b,h), round to fp16.
// grid = BATCH*NH = 64 CTAs, 256 threads.
// ---------------------------------------------------------------------------
__global__ __launch_bounds__(256)
void kv_sum()
{
    const int bh = blockIdx.x;
    const float* pb = g_kvp + (long)bh * KVC * HD * HD;
    __half* out = g_kv16 + (long)bh * HD * HD;
    #pragma unroll
    for (int r = 0; r < 16; ++r) {
        int idx = threadIdx.x + 256 * r;        // 4096 elements
        float s = 0.0f;
        #pragma unroll
        for (int c = 0; c < KVC; ++c) s += pb[c * HD * HD + idx];
        out[idx] = __float2half_rn(s);
    }
}

// ---------------------------------------------------------------------------
// kv_mt (tensor): MT[j, h*64+d] = sum_e OW[j, h*64+e] * kv16[b,h,d,e].
// A = OW tile [128 j, 64 e] (fp32->fp16 in smem), B = kv16 [64 d, 64 e].
// grid = (DIM/128, NH, BATCH), 128 threads (4 warps, each 32 j-rows x 64 d).
// ---------------------------------------------------------------------------
#define RSM 72   // smem row stride in halves (64 data + 8 pad) = 144B
__global__ __launch_bounds__(128)
void kv_mt(const float* __restrict__ OW)
{
    __shared__ __align__(16) __half ows[128 * RSM];
    __shared__ __align__(16) __half kvs[64 * RSM];

    const int jt = blockIdx.x, hh = blockIdx.y, b = blockIdx.z;
    const int tid  = threadIdx.x;
    const int wid  = tid >> 5;
    const int lane = tid & 31;
    const int j0   = jt * 128;

    // Load OW tile [128][64] fp32 -> fp16 smem (e contiguous, coalesced)
    {
        const float* src = OW + (long)j0 * DIM + hh * HD;
        #pragma unroll
        for (int i = 0; i < 32; ++i) {
            int idx = i * 256 + tid * 2;        // 8192 elements, 2 per thread-slot
            int row = idx >> 6, e = idx & 63;
            float2 v = *(const float2*)(src + (long)row * DIM + e);
            *(uint32_t*)&ows[row * RSM + e] = pack2h(v.x, v.y);
        }
    }
    // Load kv16 tile [64][64] (already fp16)
    {
        const __half* src = g_kv16 + (long)(b * NH + hh) * HD * HD;
        #pragma unroll
        for (int i = 0; i < 4; ++i) {
            int idx = i * 128 + tid;            // 512 slots of 8 halves
            int row = idx >> 3, c8 = (idx & 7) * 8;
            uint4 v = *(const uint4*)(src + row * HD + c8);
            *(uint4*)&kvs[row * RSM + c8] = v;
        }
    }
    __syncthreads();

    const uint32_t sOW = smem_u32(ows);
    const uint32_t sKV = smem_u32(kvs);

    // ldmatrix per-lane address parts (identical geometry to the big GEMM)
    const uint32_t rA  = lane & 15;
    const uint32_t kAp = (uint32_t)(lane >> 4) << 4;
    const uint32_t rB  = (lane & 7) + ((lane & 16) >> 1);
    const uint32_t kBp = (lane & 8) << 1;

    const int wm = wid * 32;                    // j-rows per warp

    float acc[2][8][4] = {};

    #pragma unroll
    for (int ks = 0; ks < 4; ++ks) {
        const uint32_t kb = ks * 32;            // 16 e-elements = 32 bytes
        uint32_t af[2][4], bf[8][2];

        #pragma unroll
        for (int mt = 0; mt < 2; ++mt) {
            const uint32_t aa = sOW + (uint32_t)(wm + mt * 16 + rA) * (RSM * 2) + kAp + kb;
            LDSM_X4(af[mt][0], af[mt][1], af[mt][2], af[mt][3], aa);
        }
        #pragma unroll
        for (int ntp = 0; ntp < 4; ++ntp) {
            const uint32_t ba = sKV + (uint32_t)(ntp * 16 + rB) * (RSM * 2) + kBp + kb;
            LDSM_X4(bf[2*ntp][0], bf[2*ntp][1], bf[2*ntp+1][0], bf[2*ntp+1][1], ba);
        }

        #pragma unroll
        for (int mt = 0; mt < 2; ++mt)
            #pragma unroll
            for (int nt = 0; nt < 8; ++nt)
                mma16816(acc[mt][nt], af[mt], bf[nt]);
    }

    // Epilogue: MT[j0+row, h*64 + d], fp16
    const int lr = lane >> 2, lc2 = (lane & 3) * 2;
    __half* out = g_mtf + (long)b * DIM * DIM + hh * HD;

    #pragma unroll
    for (int mt = 0; mt < 2; ++mt) {
        #pragma unroll
        for (int nt = 0; nt < 8; ++nt) {
            const int row = j0 + wm + mt * 16 + lr;
            const int d   = nt * 8 + lc2;
            *(uint32_t*)(out + (long)row * DIM + d) =
                pack2h(acc[mt][nt][0], acc[mt][nt][1]);
            *(uint32_t*)(out + (long)(row + 8) * DIM + d) =
                pack2h(acc[mt][nt][2], acc[mt][nt][3]);
        }
    }
}

// ---------------------------------------------------------------------------
// Launch
// ---------------------------------------------------------------------------
extern "C" void kernel_launch(void* const* d_in, const int* in_sizes, int n_in,
                              void* d_out, int out_size)
{
    (void)in_sizes; (void)n_in; (void)out_size;
    const float* x  = (const float*)d_in[0];
    const float* qw = (const float*)d_in[1];
    const float* qb = (const float*)d_in[2];
    const float* kw = (const float*)d_in[3];
    const float* kb = (const float*)d_in[4];
    const float* vw = (const float*)d_in[5];
    const float* vb = (const float*)d_in[6];
    const float* ow = (const float*)d_in[7];
    const float* ob = (const float*)d_in[8];
    float* y = (float*)d_out;

    cudaFuncSetAttribute(gemm_qkv, cudaFuncAttributeMaxDynamicSharedMemorySize, GSMEM);
    cudaFuncSetAttribute(gemm_out, cudaFuncAttributeMaxDynamicSharedMemorySize, GSMEM);

    // 0) round x and all three weight matrices to fp16 in one launch
    round_all<<<XBLK + 3 * WBLK, 256>>>(x, qw, kw, vw);

    // 1) fused QKV projections (z selects q/k/v)
    gemm_qkv<<<dim3(DIM / TN, (BATCH * SEQ) / TM, 3), 128, GSMEM>>>(qb, kb, vb);

    // 2) kv state partials on tensor cores
    kv_mma<<<dim3(KVC, NH, BATCH), 128>>>();

    // 3a) sum partials -> fp16 kv state
    kv_sum<<<BATCH * NH, 256>>>();

    // 3b) fold o_w into kv state on tensor cores -> fp16 MT
    kv_mt<<<dim3(DIM / 128, NH, BATCH), 128>>>(ow);

    // 4) y[b] = q[b] @ MT[b]^T + o_b
    gemm_out<<<dim3(DIM / TN, SEQ / TM, BATCH), 128, GSMEM>>>(ob, y);
}

// round 14
// speedup vs baseline: 1.2084x; 1.0133x over previous
#include <cuda_runtime.h>
#include <cuda_fp16.h>
#include <cstdint>

// Problem constants
#define BATCH 4
#define SEQ   4096
#define DIM   1024
#define NH    16
#define HD    64
#define KVC   8               // split-S chunks for kv accumulation
#define SCH   (SEQ / KVC)     // 512

// GEMM tile config (proven R9 configuration — FROZEN)
#define GK      1024
#define TM      128
#define TN      128
#define BK      32                   // K elements per chunk
#define NCHUNK  (GK / BK)            // 32
#define RS      40                   // smem row stride in fp16 (32 data + 8 pad) = 80B
#define TILE_B  (128 * RS * 2)       // 10240 bytes per tile
#define STAGE_B (2 * TILE_B)         // A, B = 20480 bytes
#define NSTAGE  4
#define GSMEM   (NSTAGE * STAGE_B)   // 81920 bytes -> 2 CTAs/SM

// kv tile config
#define RSK     72                   // kv smem row stride halves (64 + 8 pad) = 144B
#define KVTILE  (64 * RSK * 2)       // 9216 bytes

// ---------------------------------------------------------------------------
// Scratch
// ---------------------------------------------------------------------------
__device__ __half g_x16[BATCH * SEQ * DIM];
__device__ __half g_qw16[DIM * DIM], g_kw16[DIM * DIM], g_vw16[DIM * DIM];
__device__ __half g_q16[BATCH * SEQ * DIM];
__device__ __half g_k16[BATCH * SEQ * DIM];
__device__ __half g_v16[BATCH * SEQ * DIM];
__device__ float  g_kvp[BATCH * NH * KVC * HD * HD];
__device__ __half g_kv16[BATCH * NH * HD * HD];
__device__ __half g_mtf[BATCH * DIM * DIM];

// ---------------------------------------------------------------------------
// PTX helpers
// ---------------------------------------------------------------------------
__device__ __forceinline__ uint32_t smem_u32(const void* p) {
    uint32_t a;
    asm("{ .reg .u64 t; cvta.to.shared.u64 t, %1; cvt.u32.u64 %0, t; }" : "=r"(a) : "l"(p));
    return a;
}

#define CP_ASYNC16(s, g) asm volatile("cp.async.cg.shared.global [%0], [%1], 16;" :: "r"(s), "l"(g))
#define CP_COMMIT()      asm volatile("cp.async.commit_group;" ::: "memory")
#define CP_WAIT2()       asm volatile("cp.async.wait_group 2;" ::: "memory")
#define CP_WAIT1()       asm volatile("cp.async.wait_group 1;" ::: "memory")
#define CP_WAIT0()       asm volatile("cp.async.wait_group 0;" ::: "memory")

#define LDSM_X4(r0, r1, r2, r3, a) \
    asm volatile("ldmatrix.sync.aligned.m8n8.x4.shared.b16 {%0,%1,%2,%3}, [%4];" \
                 : "=r"(r0), "=r"(r1), "=r"(r2), "=r"(r3) : "r"(a))
#define LDSM_X4_T(r0, r1, r2, r3, a) \
    asm volatile("ldmatrix.sync.aligned.m8n8.x4.trans.shared.b16 {%0,%1,%2,%3}, [%4];" \
                 : "=r"(r0), "=r"(r1), "=r"(r2), "=r"(r3) : "r"(a))

// D += A * B  (m16n8k16, fp16 in, f32 accum)
__device__ __forceinline__ void mma16816(float* c, const uint32_t* a, const uint32_t* b) {
    asm volatile(
        "mma.sync.aligned.m16n8k16.row.col.f32.f16.f16.f32 "
        "{%0,%1,%2,%3}, {%4,%5,%6,%7}, {%8,%9}, {%0,%1,%2,%3};"
        : "+f"(c[0]), "+f"(c[1]), "+f"(c[2]), "+f"(c[3])
        : "r"(a[0]), "r"(a[1]), "r"(a[2]), "r"(a[3]), "r"(b[0]), "r"(b[1]));
}

__device__ __forceinline__ uint32_t pack2h(float lo_v, float hi_v) {
    uint32_t r;
    asm("cvt.rn.f16x2.f32 %0, %1, %2;" : "=r"(r) : "f"(hi_v), "f"(lo_v));
    return r;
}

// ---------------------------------------------------------------------------
// Merged rounding kernel: fp32 -> fp16 for x (16384 blocks) + qw/kw/vw (1024 each)
// ---------------------------------------------------------------------------
#define XBLK 16384
#define WBLK 1024
__global__ void round_all(const float* __restrict__ x,
                          const float* __restrict__ qw, const float* __restrict__ kw,
                          const float* __restrict__ vw)
{
    int bid = blockIdx.x;
    const float* s;
    __half* o;
    long base;
    if (bid < XBLK) {
        s = x; o = g_x16; base = (long)bid * 1024;
    } else if (bid < XBLK + WBLK) {
        s = qw; o = g_qw16; base = (long)(bid - XBLK) * 1024;
    } else if (bid < XBLK + 2 * WBLK) {
        s = kw; o = g_kw16; base = (long)(bid - XBLK - WBLK) * 1024;
    } else {
        s = vw; o = g_vw16; base = (long)(bid - XBLK - 2 * WBLK) * 1024;
    }
    long i = base + (long)threadIdx.x * 4;
    float4 v = *(const float4*)(s + i);
    *(uint2*)(o + i) = make_uint2(pack2h(v.x, v.y), pack2h(v.z, v.w));
}

// ---------------------------------------------------------------------------
// Shared GEMM mainloop (R9-proven, FROZEN): 128 threads, 4 warps (2x2),
// warp tile 64x64. acc[4][8][4] += A*B^T. BK=32, 4-stage ring.
// ---------------------------------------------------------------------------
__device__ __forceinline__ void gemm_mainloop(
    const __half* __restrict__ A, const __half* __restrict__ B,
    uint32_t smem_addr, int m0, int n0, int tid, float acc[4][8][4])
{
    const int wid  = tid >> 5;
    const int lane = tid & 31;

    uint32_t so[4];
    long ga[4], gb[4];
    #pragma unroll
    for (int i = 0; i < 4; ++i) {
        int idx = i * 128 + tid;
        int row = idx >> 2, ck = idx & 3;
        so[i] = (uint32_t)(row * RS + ck * 8) * 2;
        ga[i] = (long)(m0 + row) * GK + ck * 8;
        gb[i] = (long)(n0 + row) * GK + ck * 8;
    }

    auto load_stage = [&](int kt, int buf) {
        const uint32_t sb = smem_addr + buf * STAGE_B;
        const long ko = (long)kt * BK;
        #pragma unroll
        for (int i = 0; i < 4; ++i) CP_ASYNC16(sb + so[i],          A + ga[i] + ko);
        #pragma unroll
        for (int i = 0; i < 4; ++i) CP_ASYNC16(sb + TILE_B + so[i], B + gb[i] + ko);
    };

    load_stage(0, 0); CP_COMMIT();
    load_stage(1, 1); CP_COMMIT();
    load_stage(2, 2); CP_COMMIT();

    const int wm = (wid >> 1) * 64;
    const int wn = (wid & 1) * 64;

    const uint32_t rA  = lane & 15;
    const uint32_t kAp = (uint32_t)(lane >> 4) << 4;
    const uint32_t rB  = (lane & 7) + ((lane & 16) >> 1);
    const uint32_t kBp = (lane & 8) << 1;

    uint32_t offA[4], offB[4];
    #pragma unroll
    for (int mt = 0; mt < 4; ++mt)
        offA[mt] = (uint32_t)(wm + mt * 16 + rA) * (RS * 2) + kAp;
    #pragma unroll
    for (int ntp = 0; ntp < 4; ++ntp)
        offB[ntp] = (uint32_t)(wn + ntp * 16 + rB) * (RS * 2) + kBp;

    for (int kt = 0; kt < NCHUNK; ++kt) {
        CP_WAIT2();
        __syncthreads();

        if (kt + 3 < NCHUNK) load_stage(kt + 3, (kt + 3) & 3);
        CP_COMMIT();

        const uint32_t Sb = smem_addr + (kt & 3) * STAGE_B;

        #pragma unroll
        for (int ks2 = 0; ks2 < 2; ++ks2) {
            const uint32_t kb = ks2 * 32;
            uint32_t af[4][4], bf[8][2];

            #pragma unroll
            for (int mt = 0; mt < 4; ++mt)
                LDSM_X4(af[mt][0], af[mt][1], af[mt][2], af[mt][3], Sb + kb + offA[mt]);
            #pragma unroll
            for (int ntp = 0; ntp < 4; ++ntp) {
                const uint32_t ba = Sb + TILE_B + kb + offB[ntp];
                LDSM_X4(bf[2*ntp][0], bf[2*ntp][1], bf[2*ntp+1][0], bf[2*ntp+1][1], ba);
            }

            #pragma unroll
            for (int mt = 0; mt < 4; ++mt)
                #pragma unroll
                for (int nt = 0; nt < 8; ++nt)
                    mma16816(acc[mt][nt], af[mt], bf[nt]);
        }
    }
}

// ---------------------------------------------------------------------------
// Fused QKV GEMM: blockIdx.z selects (W, bias, out, relu). fp16 out.
// ---------------------------------------------------------------------------
__global__ __launch_bounds__(128, 2)
void gemm_qkv(const float* __restrict__ qb, const float* __restrict__ kb,
              const float* __restrict__ vb)
{
    extern __shared__ char smem[];
    const uint32_t smem_addr = smem_u32(smem);

    const int tid = threadIdx.x;
    const int z   = blockIdx.z;
    const int m0  = blockIdx.y * TM;
    const int n0  = blockIdx.x * TN;

    const __half* B    = (z == 0) ? g_qw16 : (z == 1) ? g_kw16 : g_vw16;
    const float*  bias = (z == 0) ? qb     : (z == 1) ? kb     : vb;
    __half*       outH = (z == 0) ? g_q16  : (z == 1) ? g_k16  : g_v16;
    const bool    relu = (z != 2);

    float acc[4][8][4] = {};
    gemm_mainloop(g_x16, B, smem_addr, m0, n0, tid, acc);

    const int wid  = tid >> 5;
    const int lane = tid & 31;
    const int wm = (wid >> 1) * 64, wn = (wid & 1) * 64;
    const int lr = lane >> 2, lc2 = (lane & 3) * 2;

    #pragma unroll
    for (int mt = 0; mt < 4; ++mt) {
        #pragma unroll
        for (int nt = 0; nt < 8; ++nt) {
            const int row = m0 + wm + mt * 16 + lr;
            const int col = n0 + wn + nt * 8 + lc2;
            const float2 bv = *(const float2*)(bias + col);
            float v00 = acc[mt][nt][0] + bv.x, v01 = acc[mt][nt][1] + bv.y;
            float v10 = acc[mt][nt][2] + bv.x, v11 = acc[mt][nt][3] + bv.y;
            if (relu) {
                v00 = fmaxf(v00, 0.f); v01 = fmaxf(v01, 0.f);
                v10 = fmaxf(v10, 0.f); v11 = fmaxf(v11, 0.f);
            }
            const long o = (long)row * DIM + col;
            *(uint32_t*)(outH + o)            = pack2h(v00, v01);
            *(uint32_t*)(outH + o + 8L * DIM) = pack2h(v10, v11);
        }
    }
}

// ---------------------------------------------------------------------------
// Final GEMM: y[b] = q[b] @ MT[b]^T + o_b  (fp32 out)
// ---------------------------------------------------------------------------
__global__ __launch_bounds__(128, 2)
void gemm_out(const float* __restrict__ bias, float* __restrict__ outF)
{
    extern __shared__ char smem[];
    const uint32_t smem_addr = smem_u32(smem);

    const int tid = threadIdx.x;
    const int z   = blockIdx.z;
    const int m0  = blockIdx.y * TM;
    const int n0  = blockIdx.x * TN;

    const __half* A = g_q16 + (long)z * SEQ * DIM;
    const __half* B = g_mtf + (long)z * DIM * DIM;

    float acc[4][8][4] = {};
    gemm_mainloop(A, B, smem_addr, m0, n0, tid, acc);

    const int wid  = tid >> 5;
    const int lane = tid & 31;
    const int wm = (wid >> 1) * 64, wn = (wid & 1) * 64;
    const int lr = lane >> 2, lc2 = (lane & 3) * 2;

    float* out = outF + (long)z * SEQ * DIM;

    #pragma unroll
    for (int mt = 0; mt < 4; ++mt) {
        #pragma unroll
        for (int nt = 0; nt < 8; ++nt) {
            const int row = m0 + wm + mt * 16 + lr;
            const int col = n0 + wn + nt * 8 + lc2;
            const float2 bv = *(const float2*)(bias + col);
            float* p = out + (long)row * DIM + col;
            *(float2*)p              = make_float2(acc[mt][nt][0] + bv.x, acc[mt][nt][1] + bv.y);
            *(float2*)(p + 8L * DIM) = make_float2(acc[mt][nt][2] + bv.x, acc[mt][nt][3] + bv.y);
        }
    }
}

// ---------------------------------------------------------------------------
// kv partials on tensor cores: P[b,h,c,d,e] = sum_{s in chunk} k[s,d]*v[s,e].
// ---------------------------------------------------------------------------
__global__ __launch_bounds__(128)
void kv_mma()
{
    __shared__ __align__(16) char kvsm[2 * 2 * KVTILE];  // [buf][k/v][tile]

    const int c = blockIdx.x, hh = blockIdx.y, b = blockIdx.z;
    const int tid  = threadIdx.x;
    const int wid  = tid >> 5;
    const int lane = tid & 31;
    const uint32_t sbase = smem_u32(kvsm);

    const __half* kb = g_k16 + (long)(b * SEQ + c * SCH) * DIM + hh * HD;
    const __half* vb = g_v16 + (long)(b * SEQ + c * SCH) * DIM + hh * HD;

    uint32_t so[4];
    long go[4];
    #pragma unroll
    for (int i = 0; i < 4; ++i) {
        int idx = i * 128 + tid;
        int row = idx >> 3, ck = idx & 7;
        so[i] = (uint32_t)(row * RSK + ck * 8) * 2;
        go[i] = (long)row * DIM + ck * 8;
    }

    auto load_blk = [&](int blk, int buf) {
        const uint32_t sb = sbase + buf * 2 * KVTILE;
        const long ko = (long)blk * 64 * DIM;
        #pragma unroll
        for (int i = 0; i < 4; ++i) CP_ASYNC16(sb + so[i],          kb + ko + go[i]);
        #pragma unroll
        for (int i = 0; i < 4; ++i) CP_ASYNC16(sb + KVTILE + so[i], vb + ko + go[i]);
    };

    load_blk(0, 0); CP_COMMIT();

    const uint32_t rKA = (lane & 7) + ((lane & 16) >> 1);
    const uint32_t mAp = (lane & 8) << 1;
    const uint32_t rVB = lane & 15;
    const uint32_t nBp = (uint32_t)(lane >> 4) << 4;

    const int wn = wid * 16;   // e-range per warp

    float acc[4][2][4] = {};

    for (int blk = 0; blk < SCH / 64; ++blk) {
        if (blk + 1 < SCH / 64) load_blk(blk + 1, (blk + 1) & 1);
        CP_COMMIT();
        if (blk + 1 < SCH / 64) { CP_WAIT1(); } else { CP_WAIT0(); }
        __syncthreads();

        const uint32_t Sk = sbase + (blk & 1) * 2 * KVTILE;
        const uint32_t Sv = Sk + KVTILE;

        #pragma unroll
        for (int ks = 0; ks < 4; ++ks) {
            const uint32_t srow = ks * 16;
            uint32_t af[4][4], bf[2][2];

            #pragma unroll
            for (int mt = 0; mt < 4; ++mt) {
                const uint32_t aa = Sk + (srow + rKA) * (RSK * 2) + mt * 32 + mAp;
                LDSM_X4_T(af[mt][0], af[mt][1], af[mt][2], af[mt][3], aa);
            }
            {
                const uint32_t ba = Sv + (srow + rVB) * (RSK * 2) + wn * 2 + nBp;
                LDSM_X4_T(bf[0][0], bf[0][1], bf[1][0], bf[1][1], ba);
            }

            #pragma unroll
            for (int mt = 0; mt < 4; ++mt)
                #pragma unroll
                for (int nt = 0; nt < 2; ++nt)
                    mma16816(acc[mt][nt], af[mt], bf[nt]);
        }
        __syncthreads();
    }

    const int lr = lane >> 2, lc2 = (lane & 3) * 2;
    float* out = g_kvp + ((long)((b * NH + hh) * KVC + c)) * HD * HD;
    #pragma unroll
    for (int mt = 0; mt < 4; ++mt) {
        #pragma unroll
        for (int nt = 0; nt < 2; ++nt) {
            const int d = mt * 16 + lr;
            const int e = wn + nt * 8 + lc2;
            *(float2*)(out + (long)d * HD + e)       = make_float2(acc[mt][nt][0], acc[mt][nt][1]);
            *(float2*)(out + (long)(d + 8) * HD + e) = make_float2(acc[mt][nt][2], acc[mt][nt][3]);
        }
    }
}

// ---------------------------------------------------------------------------
// kv_sum: sum the KVC fp32 partials per (b,h), round to fp16.
// Full-chip grid: 256 CTAs x 256 threads; each thread owns 4 consecutive
// outputs (float4 loads, uint2 fp16 store). 65536 threads total.
// ---------------------------------------------------------------------------
__global__ __launch_bounds__(256)
void kv_sum()
{
    const int gthread = blockIdx.x * 256 + threadIdx.x;   // 0..65535
    const int bh   = gthread >> 10;                       // 64 (b,h) slices
    const int idx4 = (gthread & 1023) * 4;                // 0..4092

    const float* pb = g_kvp + (long)bh * KVC * HD * HD + idx4;
    float4 s = *(const float4*)pb;
    #pragma unroll
    for (int c = 1; c < KVC; ++c) {
        float4 v = *(const float4*)(pb + c * HD * HD);
        s.x += v.x; s.y += v.y; s.z += v.z; s.w += v.w;
    }
    __half* out = g_kv16 + (long)bh * HD * HD + idx4;
    *(uint2*)out = make_uint2(pack2h(s.x, s.y), pack2h(s.z, s.w));
}

// ---------------------------------------------------------------------------
// kv_mt (tensor): MT[j, h*64+d] = sum_e OW[j, h*64+e] * kv16[b,h,d,e].
// A = OW tile [128 j, 64 e] (fp32->fp16 in smem), B = kv16 [64 d, 64 e].
// grid = (DIM/128, NH, BATCH), 128 threads (4 warps, each 32 j-rows x 64 d).
// ---------------------------------------------------------------------------
#define RSM 72   // smem row stride in halves (64 data + 8 pad) = 144B
__global__ __launch_bounds__(128)
void kv_mt(const float* __restrict__ OW)
{
    __shared__ __align__(16) __half ows[128 * RSM];
    __shared__ __align__(16) __half kvs[64 * RSM];

    const int jt = blockIdx.x, hh = blockIdx.y, b = blockIdx.z;
    const int tid  = threadIdx.x;
    const int wid  = tid >> 5;
    const int lane = tid & 31;
    const int j0   = jt * 128;

    // Load OW tile [128][64] fp32 -> fp16 smem (e contiguous, coalesced)
    {
        const float* src = OW + (long)j0 * DIM + hh * HD;
        #pragma unroll
        for (int i = 0; i < 32; ++i) {
            int idx = i * 256 + tid * 2;        // 8192 elements, 2 per thread-slot
            int row = idx >> 6, e = idx & 63;
            float2 v = *(const float2*)(src + (long)row * DIM + e);
            *(uint32_t*)&ows[row * RSM + e] = pack2h(v.x, v.y);
        }
    }
    // Load kv16 tile [64][64] (already fp16)
    {
        const __half* src = g_kv16 + (long)(b * NH + hh) * HD * HD;
        #pragma unroll
        for (int i = 0; i < 4; ++i) {
            int idx = i * 128 + tid;            // 512 slots of 8 halves
            int row = idx >> 3, c8 = (idx & 7) * 8;
            uint4 v = *(const uint4*)(src + row * HD + c8);
            *(uint4*)&kvs[row * RSM + c8] = v;
        }
    }
    __syncthreads();

    const uint32_t sOW = smem_u32(ows);
    const uint32_t sKV = smem_u32(kvs);

    // ldmatrix per-lane address parts (identical geometry to the big GEMM)
    const uint32_t rA  = lane & 15;
    const uint32_t kAp = (uint32_t)(lane >> 4) << 4;
    const uint32_t rB  = (lane & 7) + ((lane & 16) >> 1);
    const uint32_t kBp = (lane & 8) << 1;

    const int wm = wid * 32;                    // j-rows per warp

    float acc[2][8][4] = {};

    #pragma unroll
    for (int ks = 0; ks < 4; ++ks) {
        const uint32_t kb = ks * 32;            // 16 e-elements = 32 bytes
        uint32_t af[2][4], bf[8][2];

        #pragma unroll
        for (int mt = 0; mt < 2; ++mt) {
            const uint32_t aa = sOW + (uint32_t)(wm + mt * 16 + rA) * (RSM * 2) + kAp + kb;
            LDSM_X4(af[mt][0], af[mt][1], af[mt][2], af[mt][3], aa);
        }
        #pragma unroll
        for (int ntp = 0; ntp < 4; ++ntp) {
            const uint32_t ba = sKV + (uint32_t)(ntp * 16 + rB) * (RSM * 2) + kBp + kb;
            LDSM_X4(bf[2*ntp][0], bf[2*ntp][1], bf[2*ntp+1][0], bf[2*ntp+1][1], ba);
        }

        #pragma unroll
        for (int mt = 0; mt < 2; ++mt)
            #pragma unroll
            for (int nt = 0; nt < 8; ++nt)
                mma16816(acc[mt][nt], af[mt], bf[nt]);
    }

    // Epilogue: MT[j0+row, h*64 + d], fp16
    const int lr = lane >> 2, lc2 = (lane & 3) * 2;
    __half* out = g_mtf + (long)b * DIM * DIM + hh * HD;

    #pragma unroll
    for (int mt = 0; mt < 2; ++mt) {
        #pragma unroll
        for (int nt = 0; nt < 8; ++nt) {
            const int row = j0 + wm + mt * 16 + lr;
            const int d   = nt * 8 + lc2;
            *(uint32_t*)(out + (long)row * DIM + d) =
                pack2h(acc[mt][nt][0], acc[mt][nt][1]);
            *(uint32_t*)(out + (long)(row + 8) * DIM + d) =
                pack2h(acc[mt][nt][2], acc[mt][nt][3]);
        }
    }
}

// ---------------------------------------------------------------------------
// Launch
// ---------------------------------------------------------------------------
extern "C" void kernel_launch(void* const* d_in, const int* in_sizes, int n_in,
                              void* d_out, int out_size)
{
    (void)in_sizes; (void)n_in; (void)out_size;
    const float* x  = (const float*)d_in[0];
    const float* qw = (const float*)d_in[1];
    const float* qb = (const float*)d_in[2];
    const float* kw = (const float*)d_in[3];
    const float* kb = (const float*)d_in[4];
    const float* vw = (const float*)d_in[5];
    const float* vb = (const float*)d_in[6];
    const float* ow = (const float*)d_in[7];
    const float* ob = (const float*)d_in[8];
    float* y = (float*)d_out;

    cudaFuncSetAttribute(gemm_qkv, cudaFuncAttributeMaxDynamicSharedMemorySize, GSMEM);
    cudaFuncSetAttribute(gemm_out, cudaFuncAttributeMaxDynamicSharedMemorySize, GSMEM);

    // 0) round x and all three weight matrices to fp16 in one launch
    round_all<<<XBLK + 3 * WBLK, 256>>>(x, qw, kw, vw);

    // 1) fused QKV projections (z selects q/k/v)
    gemm_qkv<<<dim3(DIM / TN, (BATCH * SEQ) / TM, 3), 128, GSMEM>>>(qb, kb, vb);

    // 2) kv state partials on tensor cores
    kv_mma<<<dim3(KVC, NH, BATCH), 128>>>();

    // 3a) sum partials -> fp16 kv state (full-chip grid)
    kv_sum<<<256, 256>>>();

    // 3b) fold o_w into kv state on tensor cores -> fp16 MT
    kv_mt<<<dim3(DIM / 128, NH, BATCH), 128>>>(ow);

    // 4) y[b] = q[b] @ MT[b]^T + o_b
    gemm_out<<<dim3(DIM / TN, SEQ / TM, BATCH), 128, GSMEM>>>(ob, y);
}

// round 15
// speedup vs baseline: 1.2251x; 1.0138x over previous
#include <cuda_runtime.h>
#include <cuda_fp16.h>
#include <cstdint>

// Problem constants
#define BATCH 4
#define SEQ   4096
#define DIM   1024
#define NH    16
#define HD    64
#define KVC   8               // split-S chunks for kv accumulation
#define SCH   (SEQ / KVC)     // 512

// GEMM tile config (proven R9 configuration — FROZEN)
#define GK      1024
#define TM      128
#define TN      128
#define BK      32                   // K elements per chunk
#define NCHUNK  (GK / BK)            // 32
#define RS      40                   // smem row stride in fp16 (32 data + 8 pad) = 80B
#define TILE_B  (128 * RS * 2)       // 10240 bytes per tile
#define STAGE_B (2 * TILE_B)         // A, B = 20480 bytes
#define NSTAGE  4
#define GSMEM   (NSTAGE * STAGE_B)   // 81920 bytes -> 2 CTAs/SM

// kv tile config
#define RSK     72                   // kv smem row stride halves (64 + 8 pad) = 144B
#define KVTILE  (64 * RSK * 2)       // 9216 bytes

// ---------------------------------------------------------------------------
// Scratch
// ---------------------------------------------------------------------------
__device__ __half g_x16[BATCH * SEQ * DIM];
__device__ __half g_qw16[DIM * DIM], g_kw16[DIM * DIM], g_vw16[DIM * DIM];
__device__ __half g_q16[BATCH * SEQ * DIM];
__device__ __half g_k16[BATCH * SEQ * DIM];
__device__ __half g_v16[BATCH * SEQ * DIM];
__device__ float  g_kvp[BATCH * NH * KVC * HD * HD];
__device__ __half g_mtf[BATCH * DIM * DIM];

// ---------------------------------------------------------------------------
// PTX helpers
// ---------------------------------------------------------------------------
__device__ __forceinline__ uint32_t smem_u32(const void* p) {
    uint32_t a;
    asm("{ .reg .u64 t; cvta.to.shared.u64 t, %1; cvt.u32.u64 %0, t; }" : "=r"(a) : "l"(p));
    return a;
}

#define CP_ASYNC16(s, g) asm volatile("cp.async.cg.shared.global [%0], [%1], 16;" :: "r"(s), "l"(g))
#define CP_COMMIT()      asm volatile("cp.async.commit_group;" ::: "memory")
#define CP_WAIT2()       asm volatile("cp.async.wait_group 2;" ::: "memory")
#define CP_WAIT1()       asm volatile("cp.async.wait_group 1;" ::: "memory")
#define CP_WAIT0()       asm volatile("cp.async.wait_group 0;" ::: "memory")

#define LDSM_X4(r0, r1, r2, r3, a) \
    asm volatile("ldmatrix.sync.aligned.m8n8.x4.shared.b16 {%0,%1,%2,%3}, [%4];" \
                 : "=r"(r0), "=r"(r1), "=r"(r2), "=r"(r3) : "r"(a))
#define LDSM_X4_T(r0, r1, r2, r3, a) \
    asm volatile("ldmatrix.sync.aligned.m8n8.x4.trans.shared.b16 {%0,%1,%2,%3}, [%4];" \
                 : "=r"(r0), "=r"(r1), "=r"(r2), "=r"(r3) : "r"(a))

// D += A * B  (m16n8k16, fp16 in, f32 accum)
__device__ __forceinline__ void mma16816(float* c, const uint32_t* a, const uint32_t* b) {
    asm volatile(
        "mma.sync.aligned.m16n8k16.row.col.f32.f16.f16.f32 "
        "{%0,%1,%2,%3}, {%4,%5,%6,%7}, {%8,%9}, {%0,%1,%2,%3};"
        : "+f"(c[0]), "+f"(c[1]), "+f"(c[2]), "+f"(c[3])
        : "r"(a[0]), "r"(a[1]), "r"(a[2]), "r"(a[3]), "r"(b[0]), "r"(b[1]));
}

__device__ __forceinline__ uint32_t pack2h(float lo_v, float hi_v) {
    uint32_t r;
    asm("cvt.rn.f16x2.f32 %0, %1, %2;" : "=r"(r) : "f"(hi_v), "f"(lo_v));
    return r;
}

// ---------------------------------------------------------------------------
// Merged rounding kernel, MLP=4: each thread converts 4 float4s (16 elems).
// Block covers 4096 elems. x: 4096 blocks; qw/kw/vw: 256 blocks each.
// ---------------------------------------------------------------------------
#define XBLK4 4096
#define WBLK4 256
__global__ void round_all(const float* __restrict__ x,
                          const float* __restrict__ qw, const float* __restrict__ kw,
                          const float* __restrict__ vw)
{
    int bid = blockIdx.x;
    const float* s;
    __half* o;
    long base;
    if (bid < XBLK4) {
        s = x; o = g_x16; base = (long)bid * 4096;
    } else if (bid < XBLK4 + WBLK4) {
        s = qw; o = g_qw16; base = (long)(bid - XBLK4) * 4096;
    } else if (bid < XBLK4 + 2 * WBLK4) {
        s = kw; o = g_kw16; base = (long)(bid - XBLK4 - WBLK4) * 4096;
    } else {
        s = vw; o = g_vw16; base = (long)(bid - XBLK4 - 2 * WBLK4) * 4096;
    }
    // 4 independent float4 loads per thread (MLP=4), coalesced per i
    float4 v[4];
    long off[4];
    #pragma unroll
    for (int i = 0; i < 4; ++i) {
        off[i] = base + (long)(i * 256 + threadIdx.x) * 4;
        v[i] = *(const float4*)(s + off[i]);
    }
    #pragma unroll
    for (int i = 0; i < 4; ++i)
        *(uint2*)(o + off[i]) = make_uint2(pack2h(v[i].x, v[i].y), pack2h(v[i].z, v[i].w));
}

// ---------------------------------------------------------------------------
// Shared GEMM mainloop (R9-proven, FROZEN): 128 threads, 4 warps (2x2),
// warp tile 64x64. acc[4][8][4] += A*B^T. BK=32, 4-stage ring.
// ---------------------------------------------------------------------------
__device__ __forceinline__ void gemm_mainloop(
    const __half* __restrict__ A, const __half* __restrict__ B,
    uint32_t smem_addr, int m0, int n0, int tid, float acc[4][8][4])
{
    const int wid  = tid >> 5;
    const int lane = tid & 31;

    uint32_t so[4];
    long ga[4], gb[4];
    #pragma unroll
    for (int i = 0; i < 4; ++i) {
        int idx = i * 128 + tid;
        int row = idx >> 2, ck = idx & 3;
        so[i] = (uint32_t)(row * RS + ck * 8) * 2;
        ga[i] = (long)(m0 + row) * GK + ck * 8;
        gb[i] = (long)(n0 + row) * GK + ck * 8;
    }

    auto load_stage = [&](int kt, int buf) {
        const uint32_t sb = smem_addr + buf * STAGE_B;
        const long ko = (long)kt * BK;
        #pragma unroll
        for (int i = 0; i < 4; ++i) CP_ASYNC16(sb + so[i],          A + ga[i] + ko);
        #pragma unroll
        for (int i = 0; i < 4; ++i) CP_ASYNC16(sb + TILE_B + so[i], B + gb[i] + ko);
    };

    load_stage(0, 0); CP_COMMIT();
    load_stage(1, 1); CP_COMMIT();
    load_stage(2, 2); CP_COMMIT();

    const int wm = (wid >> 1) * 64;
    const int wn = (wid & 1) * 64;

    const uint32_t rA  = lane & 15;
    const uint32_t kAp = (uint32_t)(lane >> 4) << 4;
    const uint32_t rB  = (lane & 7) + ((lane & 16) >> 1);
    const uint32_t kBp = (lane & 8) << 1;

    uint32_t offA[4], offB[4];
    #pragma unroll
    for (int mt = 0; mt < 4; ++mt)
        offA[mt] = (uint32_t)(wm + mt * 16 + rA) * (RS * 2) + kAp;
    #pragma unroll
    for (int ntp = 0; ntp < 4; ++ntp)
        offB[ntp] = (uint32_t)(wn + ntp * 16 + rB) * (RS * 2) + kBp;

    for (int kt = 0; kt < NCHUNK; ++kt) {
        CP_WAIT2();
        __syncthreads();

        if (kt + 3 < NCHUNK) load_stage(kt + 3, (kt + 3) & 3);
        CP_COMMIT();

        const uint32_t Sb = smem_addr + (kt & 3) * STAGE_B;

        #pragma unroll
        for (int ks2 = 0; ks2 < 2; ++ks2) {
            const uint32_t kb = ks2 * 32;
            uint32_t af[4][4], bf[8][2];

            #pragma unroll
            for (int mt = 0; mt < 4; ++mt)
                LDSM_X4(af[mt][0], af[mt][1], af[mt][2], af[mt][3], Sb + kb + offA[mt]);
            #pragma unroll
            for (int ntp = 0; ntp < 4; ++ntp) {
                const uint32_t ba = Sb + TILE_B + kb + offB[ntp];
                LDSM_X4(bf[2*ntp][0], bf[2*ntp][1], bf[2*ntp+1][0], bf[2*ntp+1][1], ba);
            }

            #pragma unroll
            for (int mt = 0; mt < 4; ++mt)
                #pragma unroll
                for (int nt = 0; nt < 8; ++nt)
                    mma16816(acc[mt][nt], af[mt], bf[nt]);
        }
    }
}

// ---------------------------------------------------------------------------
// Fused QKV GEMM: blockIdx.z selects (W, bias, out, relu). fp16 out.
// ---------------------------------------------------------------------------
__global__ __launch_bounds__(128, 2)
void gemm_qkv(const float* __restrict__ qb, const float* __restrict__ kb,
              const float* __restrict__ vb)
{
    extern __shared__ char smem[];
    const uint32_t smem_addr = smem_u32(smem);

    const int tid = threadIdx.x;
    const int z   = blockIdx.z;
    const int m0  = blockIdx.y * TM;
    const int n0  = blockIdx.x * TN;

    const __half* B    = (z == 0) ? g_qw16 : (z == 1) ? g_kw16 : g_vw16;
    const float*  bias = (z == 0) ? qb     : (z == 1) ? kb     : vb;
    __half*       outH = (z == 0) ? g_q16  : (z == 1) ? g_k16  : g_v16;
    const bool    relu = (z != 2);

    float acc[4][8][4] = {};
    gemm_mainloop(g_x16, B, smem_addr, m0, n0, tid, acc);

    const int wid  = tid >> 5;
    const int lane = tid & 31;
    const int wm = (wid >> 1) * 64, wn = (wid & 1) * 64;
    const int lr = lane >> 2, lc2 = (lane & 3) * 2;

    #pragma unroll
    for (int mt = 0; mt < 4; ++mt) {
        #pragma unroll
        for (int nt = 0; nt < 8; ++nt) {
            const int row = m0 + wm + mt * 16 + lr;
            const int col = n0 + wn + nt * 8 + lc2;
            const float2 bv = *(const float2*)(bias + col);
            float v00 = acc[mt][nt][0] + bv.x, v01 = acc[mt][nt][1] + bv.y;
            float v10 = acc[mt][nt][2] + bv.x, v11 = acc[mt][nt][3] + bv.y;
            if (relu) {
                v00 = fmaxf(v00, 0.f); v01 = fmaxf(v01, 0.f);
                v10 = fmaxf(v10, 0.f); v11 = fmaxf(v11, 0.f);
            }
            const long o = (long)row * DIM + col;
            *(uint32_t*)(outH + o)            = pack2h(v00, v01);
            *(uint32_t*)(outH + o + 8L * DIM) = pack2h(v10, v11);
        }
    }
}

// ---------------------------------------------------------------------------
// Final GEMM: y[b] = q[b] @ MT[b]^T + o_b  (fp32 out)
// ---------------------------------------------------------------------------
__global__ __launch_bounds__(128, 2)
void gemm_out(const float* __restrict__ bias, float* __restrict__ outF)
{
    extern __shared__ char smem[];
    const uint32_t smem_addr = smem_u32(smem);

    const int tid = threadIdx.x;
    const int z   = blockIdx.z;
    const int m0  = blockIdx.y * TM;
    const int n0  = blockIdx.x * TN;

    const __half* A = g_q16 + (long)z * SEQ * DIM;
    const __half* B = g_mtf + (long)z * DIM * DIM;

    float acc[4][8][4] = {};
    gemm_mainloop(A, B, smem_addr, m0, n0, tid, acc);

    const int wid  = tid >> 5;
    const int lane = tid & 31;
    const int wm = (wid >> 1) * 64, wn = (wid & 1) * 64;
    const int lr = lane >> 2, lc2 = (lane & 3) * 2;

    float* out = outF + (long)z * SEQ * DIM;

    #pragma unroll
    for (int mt = 0; mt < 4; ++mt) {
        #pragma unroll
        for (int nt = 0; nt < 8; ++nt) {
            const int row = m0 + wm + mt * 16 + lr;
            const int col = n0 + wn + nt * 8 + lc2;
            const float2 bv = *(const float2*)(bias + col);
            float* p = out + (long)row * DIM + col;
            *(float2*)p              = make_float2(acc[mt][nt][0] + bv.x, acc[mt][nt][1] + bv.y);
            *(float2*)(p + 8L * DIM) = make_float2(acc[mt][nt][2] + bv.x, acc[mt][nt][3] + bv.y);
        }
    }
}

// ---------------------------------------------------------------------------
// kv partials on tensor cores: P[b,h,c,d,e] = sum_{s in chunk} k[s,d]*v[s,e].
// ---------------------------------------------------------------------------
__global__ __launch_bounds__(128)
void kv_mma()
{
    __shared__ __align__(16) char kvsm[2 * 2 * KVTILE];  // [buf][k/v][tile]

    const int c = blockIdx.x, hh = blockIdx.y, b = blockIdx.z;
    const int tid  = threadIdx.x;
    const int wid  = tid >> 5;
    const int lane = tid & 31;
    const uint32_t sbase = smem_u32(kvsm);

    const __half* kb = g_k16 + (long)(b * SEQ + c * SCH) * DIM + hh * HD;
    const __half* vb = g_v16 + (long)(b * SEQ + c * SCH) * DIM + hh * HD;

    uint32_t so[4];
    long go[4];
    #pragma unroll
    for (int i = 0; i < 4; ++i) {
        int idx = i * 128 + tid;
        int row = idx >> 3, ck = idx & 7;
        so[i] = (uint32_t)(row * RSK + ck * 8) * 2;
        go[i] = (long)row * DIM + ck * 8;
    }

    auto load_blk = [&](int blk, int buf) {
        const uint32_t sb = sbase + buf * 2 * KVTILE;
        const long ko = (long)blk * 64 * DIM;
        #pragma unroll
        for (int i = 0; i < 4; ++i) CP_ASYNC16(sb + so[i],          kb + ko + go[i]);
        #pragma unroll
        for (int i = 0; i < 4; ++i) CP_ASYNC16(sb + KVTILE + so[i], vb + ko + go[i]);
    };

    load_blk(0, 0); CP_COMMIT();

    const uint32_t rKA = (lane & 7) + ((lane & 16) >> 1);
    const uint32_t mAp = (lane & 8) << 1;
    const uint32_t rVB = lane & 15;
    const uint32_t nBp = (uint32_t)(lane >> 4) << 4;

    const int wn = wid * 16;   // e-range per warp

    float acc[4][2][4] = {};

    for (int blk = 0; blk < SCH / 64; ++blk) {
        if (blk + 1 < SCH / 64) load_blk(blk + 1, (blk + 1) & 1);
        CP_COMMIT();
        if (blk + 1 < SCH / 64) { CP_WAIT1(); } else { CP_WAIT0(); }
        __syncthreads();

        const uint32_t Sk = sbase + (blk & 1) * 2 * KVTILE;
        const uint32_t Sv = Sk + KVTILE;

        #pragma unroll
        for (int ks = 0; ks < 4; ++ks) {
            const uint32_t srow = ks * 16;
            uint32_t af[4][4], bf[2][2];

            #pragma unroll
            for (int mt = 0; mt < 4; ++mt) {
                const uint32_t aa = Sk + (srow + rKA) * (RSK * 2) + mt * 32 + mAp;
                LDSM_X4_T(af[mt][0], af[mt][1], af[mt][2], af[mt][3], aa);
            }
            {
                const uint32_t ba = Sv + (srow + rVB) * (RSK * 2) + wn * 2 + nBp;
                LDSM_X4_T(bf[0][0], bf[0][1], bf[1][0], bf[1][1], ba);
            }

            #pragma unroll
            for (int mt = 0; mt < 4; ++mt)
                #pragma unroll
                for (int nt = 0; nt < 2; ++nt)
                    mma16816(acc[mt][nt], af[mt], bf[nt]);
        }
        __syncthreads();
    }

    const int lr = lane >> 2, lc2 = (lane & 3) * 2;
    float* out = g_kvp + ((long)((b * NH + hh) * KVC + c)) * HD * HD;
    #pragma unroll
    for (int mt = 0; mt < 4; ++mt) {
        #pragma unroll
        for (int nt = 0; nt < 2; ++nt) {
            const int d = mt * 16 + lr;
            const int e = wn + nt * 8 + lc2;
            *(float2*)(out + (long)d * HD + e)       = make_float2(acc[mt][nt][0], acc[mt][nt][1]);
            *(float2*)(out + (long)(d + 8) * HD + e) = make_float2(acc[mt][nt][2], acc[mt][nt][3]);
        }
    }
}

// ---------------------------------------------------------------------------
// kv_mt (tensor), with fused partial-sum: B tile = sum of 8 fp32 partials,
// rounded to fp16 in smem. MT[j, h*64+d] = sum_e OW[j,h*64+e] * kv[d,e].
// grid = (DIM/128, NH, BATCH), 128 threads (4 warps, each 32 j-rows x 64 d).
// ---------------------------------------------------------------------------
#define RSM 72   // smem row stride in halves (64 data + 8 pad) = 144B
__global__ __launch_bounds__(128)
void kv_mt(const float* __restrict__ OW)
{
    __shared__ __align__(16) __half ows[128 * RSM];
    __shared__ __align__(16) __half kvs[64 * RSM];

    const int jt = blockIdx.x, hh = blockIdx.y, b = blockIdx.z;
    const int tid  = threadIdx.x;
    const int wid  = tid >> 5;
    const int lane = tid & 31;
    const int j0   = jt * 128;

    // Load OW tile [128][64] fp32 -> fp16 smem (e contiguous, coalesced)
    {
        const float* src = OW + (long)j0 * DIM + hh * HD;
        #pragma unroll
        for (int i = 0; i < 32; ++i) {
            int idx = i * 256 + tid * 2;        // 8192 elements, 2 per thread-slot
            int row = idx >> 6, e = idx & 63;
            float2 v = *(const float2*)(src + (long)row * DIM + e);
            *(uint32_t*)&ows[row * RSM + e] = pack2h(v.x, v.y);
        }
    }
    // Fused kv_sum: sum KVC fp32 partials -> fp16 smem tile [64][64]
    {
        const float* pb = g_kvp + (long)(b * NH + hh) * KVC * HD * HD;
        #pragma unroll
        for (int i = 0; i < 8; ++i) {
            int idx = i * 128 + tid;            // 1024 float4 slots
            int row = idx >> 4, c4 = (idx & 15) * 4;
            const float* p = pb + row * HD + c4;
            float4 s = *(const float4*)p;
            #pragma unroll
            for (int c = 1; c < KVC; ++c) {
                float4 v = *(const float4*)(p + c * HD * HD);
                s.x += v.x; s.y += v.y; s.z += v.z; s.w += v.w;
            }
            *(uint2*)&kvs[row * RSM + c4] = make_uint2(pack2h(s.x, s.y), pack2h(s.z, s.w));
        }
    }
    __syncthreads();

    const uint32_t sOW = smem_u32(ows);
    const uint32_t sKV = smem_u32(kvs);

    // ldmatrix per-lane address parts (identical geometry to the big GEMM)
    const uint32_t rA  = lane & 15;
    const uint32_t kAp = (uint32_t)(lane >> 4) << 4;
    const uint32_t rB  = (lane & 7) + ((lane & 16) >> 1);
    const uint32_t kBp = (lane & 8) << 1;

    const int wm = wid * 32;                    // j-rows per warp

    float acc[2][8][4] = {};

    #pragma unroll
    for (int ks = 0; ks < 4; ++ks) {
        const uint32_t kb = ks * 32;            // 16 e-elements = 32 bytes
        uint32_t af[2][4], bf[8][2];

        #pragma unroll
        for (int mt = 0; mt < 2; ++mt) {
            const uint32_t aa = sOW + (uint32_t)(wm + mt * 16 + rA) * (RSM * 2) + kAp + kb;
            LDSM_X4(af[mt][0], af[mt][1], af[mt][2], af[mt][3], aa);
        }
        #pragma unroll
        for (int ntp = 0; ntp < 4; ++ntp) {
            const uint32_t ba = sKV + (uint32_t)(ntp * 16 + rB) * (RSM * 2) + kBp + kb;
            LDSM_X4(bf[2*ntp][0], bf[2*ntp][1], bf[2*ntp+1][0], bf[2*ntp+1][1], ba);
        }

        #pragma unroll
        for (int mt = 0; mt < 2; ++mt)
            #pragma unroll
            for (int nt = 0; nt < 8; ++nt)
                mma16816(acc[mt][nt], af[mt], bf[nt]);
    }

    // Epilogue: MT[j0+row, h*64 + d], fp16
    const int lr = lane >> 2, lc2 = (lane & 3) * 2;
    __half* out = g_mtf + (long)b * DIM * DIM + hh * HD;

    #pragma unroll
    for (int mt = 0; mt < 2; ++mt) {
        #pragma unroll
        for (int nt = 0; nt < 8; ++nt) {
            const int row = j0 + wm + mt * 16 + lr;
            const int d   = nt * 8 + lc2;
            *(uint32_t*)(out + (long)row * DIM + d) =
                pack2h(acc[mt][nt][0], acc[mt][nt][1]);
            *(uint32_t*)(out + (long)(row + 8) * DIM + d) =
                pack2h(acc[mt][nt][2], acc[mt][nt][3]);
        }
    }
}

// ---------------------------------------------------------------------------
// Launch
// ---------------------------------------------------------------------------
extern "C" void kernel_launch(void* const* d_in, const int* in_sizes, int n_in,
                              void* d_out, int out_size)
{
    (void)in_sizes; (void)n_in; (void)out_size;
    const float* x  = (const float*)d_in[0];
    const float* qw = (const float*)d_in[1];
    const float* qb = (const float*)d_in[2];
    const float* kw = (const float*)d_in[3];
    const float* kb = (const float*)d_in[4];
    const float* vw = (const float*)d_in[5];
    const float* vb = (const float*)d_in[6];
    const float* ow = (const float*)d_in[7];
    const float* ob = (const float*)d_in[8];
    float* y = (float*)d_out;

    cudaFuncSetAttribute(gemm_qkv, cudaFuncAttributeMaxDynamicSharedMemorySize, GSMEM);
    cudaFuncSetAttribute(gemm_out, cudaFuncAttributeMaxDynamicSharedMemorySize, GSMEM);

    // 0) round x and all three weight matrices to fp16 (MLP=4 per thread)
    round_all<<<XBLK4 + 3 * WBLK4, 256>>>(x, qw, kw, vw);

    // 1) fused QKV projections (z selects q/k/v)
    gemm_qkv<<<dim3(DIM / TN, (BATCH * SEQ) / TM, 3), 128, GSMEM>>>(qb, kb, vb);

    // 2) kv state partials on tensor cores
    kv_mma<<<dim3(KVC, NH, BATCH), 128>>>();

    // 3) fold o_w into kv state on tensor cores (fused partial-sum) -> fp16 MT
    kv_mt<<<dim3(DIM / 128, NH, BATCH), 128>>>(ow);

    // 4) y[b] = q[b] @ MT[b]^T + o_b
    gemm_out<<<dim3(DIM / TN, SEQ / TM, BATCH), 128, GSMEM>>>(ob, y);
}